// round 1
// baseline (speedup 1.0000x reference)
#include <cuda_runtime.h>
#include <math.h>

// ---------------------------------------------------------------------------
// Problem constants (match reference)
// ---------------------------------------------------------------------------
#define NN      2048          // N_NODES
#define SEQ     64
#define DIM     256
#define NH      8
#define DH      32
#define GHEADS  4
#define NEDGE   32768
#define NTOK    (NN*SEQ)      // 131072
#define SPH     512           // sp hidden

// ---------------------------------------------------------------------------
// Scratch (device globals; no dynamic allocation allowed)
// ---------------------------------------------------------------------------
__device__ float g_X  [NTOK*DIM];       // encoder activations
__device__ float g_QKV[NTOK*3*DIM];     // qkv
__device__ float g_T1 [NTOK*DIM];       // attn out / ff hidden
__device__ float g_T2 [NTOK*DIM];       // proj out
__device__ float g_H  [NN*DIM];         // node features
__device__ float g_HN [NN*DIM];         // h_new accumulator
__device__ float g_TH [NN*DIM];         // per-relation transformed h / pos
__device__ float g_XG [NN*GHEADS*DIM];  // GAT-transformed features
__device__ float g_AS [NN*GHEADS];
__device__ float g_AD [NN*GHEADS];
__device__ float g_M  [NN*GHEADS];      // segment max
__device__ float g_DEN[NN*GHEADS];
__device__ float g_NUM[NN*GHEADS*DIM];
__device__ float g_SPH[NN*SPH];         // sp hidden

// ---------------------------------------------------------------------------
// Helpers
// ---------------------------------------------------------------------------
__device__ __forceinline__ float lrelu(float x) { return x > 0.f ? x : 0.2f * x; }

__device__ __forceinline__ void atomicMaxF(float* addr, float v) {
    if (v >= 0.f) atomicMax((int*)addr, __float_as_int(v));
    else          atomicMin((unsigned int*)addr, __float_as_uint(v));
}

// ---------------------------------------------------------------------------
// Generic tiled fp32 GEMM: C[M,N] = A[M,K] @ B[K,N] (+bias) (+relu)
// BM=BN=64, BK=16, 256 threads, 4x4 per thread. M%64==0, N%64==0, K%16==0.
// ---------------------------------------------------------------------------
__global__ void gemm_kernel(const float* __restrict__ A, const float* __restrict__ B,
                            const float* __restrict__ bias, float* __restrict__ C,
                            int M, int N, int K, int act) {
    __shared__ float As[16][64];
    __shared__ float Bs[16][64];
    const int tid = threadIdx.x;
    const int tx = tid & 15, ty = tid >> 4;
    const int row0 = blockIdx.y * 64;
    const int col0 = blockIdx.x * 64;

    const int la_r = tid >> 2;         // 0..63
    const int la_c = (tid & 3) * 4;    // k offset
    const int lb_r = tid >> 4;         // 0..15 (k)
    const int lb_c = (tid & 15) * 4;   // n offset

    float acc[4][4] = {};
    for (int k0 = 0; k0 < K; k0 += 16) {
        #pragma unroll
        for (int i = 0; i < 4; i++)
            As[la_c + i][la_r] = A[(size_t)(row0 + la_r) * K + k0 + la_c + i];
        float4 bv = *(const float4*)&B[(size_t)(k0 + lb_r) * N + col0 + lb_c];
        Bs[lb_r][lb_c]     = bv.x;
        Bs[lb_r][lb_c + 1] = bv.y;
        Bs[lb_r][lb_c + 2] = bv.z;
        Bs[lb_r][lb_c + 3] = bv.w;
        __syncthreads();
        #pragma unroll
        for (int k = 0; k < 16; k++) {
            float a[4], b[4];
            #pragma unroll
            for (int i = 0; i < 4; i++) a[i] = As[k][ty * 4 + i];
            #pragma unroll
            for (int j = 0; j < 4; j++) b[j] = Bs[k][tx * 4 + j];
            #pragma unroll
            for (int i = 0; i < 4; i++)
                #pragma unroll
                for (int j = 0; j < 4; j++) acc[i][j] += a[i] * b[j];
        }
        __syncthreads();
    }
    #pragma unroll
    for (int i = 0; i < 4; i++) {
        int row = row0 + ty * 4 + i;
        #pragma unroll
        for (int j = 0; j < 4; j++) {
            int col = col0 + tx * 4 + j;
            float v = acc[i][j] + (bias ? bias[col] : 0.f);
            if (act == 1) v = fmaxf(v, 0.f);
            C[(size_t)row * N + col] = v;
        }
    }
}

// ---------------------------------------------------------------------------
// Token embedding + positional encoding:  x = tok_emb[tok]*16 + PE(s,d)
// grid NTOK, block 256
// ---------------------------------------------------------------------------
__global__ void embed_kernel(const float* __restrict__ tok_emb,
                             const int* __restrict__ tokens) {
    int row = blockIdx.x;            // n*SEQ + s
    int s = row & (SEQ - 1);
    int d = threadIdx.x;
    int tok = tokens[row];
    int i2 = d >> 1;
    float div = expf((float)(2 * i2) * (-logf(10000.f) / (float)DIM));
    float arg = (float)s * div;
    float pe = (d & 1) ? cosf(arg) : sinf(arg);
    g_X[(size_t)row * DIM + d] = tok_emb[(size_t)tok * DIM + d] * 16.f + pe;
}

// ---------------------------------------------------------------------------
// Attention: one block per (node, head). 64 threads (one per query row).
// Online softmax, smem-resident Q/K/V.
// ---------------------------------------------------------------------------
__global__ void attn_kernel() {
    int n = blockIdx.x >> 3;
    int h = blockIdx.x & 7;
    __shared__ float Qs[SEQ][DH + 1];
    __shared__ float Ks[SEQ][DH + 1];
    __shared__ float Vs[SEQ][DH + 1];
    const float* base = g_QKV + (size_t)n * SEQ * 3 * DIM;
    for (int e = threadIdx.x; e < SEQ * DH; e += blockDim.x) {
        int r = e >> 5, d = e & 31;
        Qs[r][d] = base[r * 3 * DIM + h * DH + d];
        Ks[r][d] = base[r * 3 * DIM + DIM + h * DH + d];
        Vs[r][d] = base[r * 3 * DIM + 2 * DIM + h * DH + d];
    }
    __syncthreads();
    int i = threadIdx.x;
    float q[DH];
    #pragma unroll
    for (int d = 0; d < DH; d++) q[d] = Qs[i][d];
    const float scale = 0.17677669529663687f;   // 1/sqrt(32)
    float m = -1e30f, l = 0.f;
    float o[DH];
    #pragma unroll
    for (int d = 0; d < DH; d++) o[d] = 0.f;
    for (int j = 0; j < SEQ; j++) {
        float s = 0.f;
        #pragma unroll
        for (int d = 0; d < DH; d++) s += q[d] * Ks[j][d];
        s *= scale;
        if (s > m) {
            float c = expf(m - s);
            l *= c;
            #pragma unroll
            for (int d = 0; d < DH; d++) o[d] *= c;
            m = s;
        }
        float p = expf(s - m);
        l += p;
        #pragma unroll
        for (int d = 0; d < DH; d++) o[d] += p * Vs[j][d];
    }
    float inv = 1.f / l;
    float* out = g_T1 + ((size_t)n * SEQ + i) * DIM + h * DH;
    #pragma unroll
    for (int d = 0; d < DH; d++) out[d] = o[d] * inv;
}

// ---------------------------------------------------------------------------
// X = LayerNorm(X + T), per row of 256. grid NTOK, block 256.
// ---------------------------------------------------------------------------
__global__ void add_ln_kernel(const float* __restrict__ T,
                              const float* __restrict__ g,
                              const float* __restrict__ b) {
    int row = blockIdx.x;
    int d = threadIdx.x;
    __shared__ float sh[256];
    __shared__ float stat;
    float v = g_X[(size_t)row * DIM + d] + T[(size_t)row * DIM + d];
    sh[d] = v; __syncthreads();
    for (int s = 128; s > 0; s >>= 1) { if (d < s) sh[d] += sh[d + s]; __syncthreads(); }
    if (d == 0) stat = sh[0] * (1.f / 256.f);
    __syncthreads();
    float mean = stat;
    float diff = v - mean;
    __syncthreads();
    sh[d] = diff * diff; __syncthreads();
    for (int s = 128; s > 0; s >>= 1) { if (d < s) sh[d] += sh[d + s]; __syncthreads(); }
    if (d == 0) stat = sh[0] * (1.f / 256.f);
    __syncthreads();
    float var = stat;
    g_X[(size_t)row * DIM + d] = diff * rsqrtf(var + 1e-5f) * g[d] + b[d];
}

// ---------------------------------------------------------------------------
// h = mean_s x + type_emb[type]. grid NN, block 256.
// ---------------------------------------------------------------------------
__global__ void mean_kernel(const int* __restrict__ types,
                            const float* __restrict__ type_emb) {
    int n = blockIdx.x, d = threadIdx.x;
    float acc = 0.f;
    const float* base = g_X + (size_t)n * SEQ * DIM + d;
    for (int s = 0; s < SEQ; s++) acc += base[s * DIM];
    g_H[(size_t)n * DIM + d] = acc * (1.f / SEQ) + type_emb[(size_t)types[n] * DIM + d];
}

// ---------------------------------------------------------------------------
// a_s[n,gh], a_d[n,gh]. grid NN, block 128 (warp per head).
// ---------------------------------------------------------------------------
__global__ void asd_kernel(const float* __restrict__ asrc,
                           const float* __restrict__ adst) {
    int n = blockIdx.x;
    int w = threadIdx.x >> 5, lane = threadIdx.x & 31;
    float s1 = 0.f, s2 = 0.f;
    const float* xg = g_XG + (size_t)n * GHEADS * DIM + w * DIM;
    #pragma unroll
    for (int d = lane; d < DIM; d += 32) {
        float xv = xg[d];
        s1 += xv * asrc[w * DIM + d];
        s2 += xv * adst[w * DIM + d];
    }
    #pragma unroll
    for (int off = 16; off > 0; off >>= 1) {
        s1 += __shfl_down_sync(0xffffffffu, s1, off);
        s2 += __shfl_down_sync(0xffffffffu, s2, off);
    }
    if (lane == 0) {
        g_AS[n * GHEADS + w] = s1;
        g_AD[n * GHEADS + w] = s2;
    }
}

// m init = e_self. NN*GHEADS elems.
__global__ void minit_kernel() {
    int i = blockIdx.x * blockDim.x + threadIdx.x;
    if (i >= NN * GHEADS) return;
    g_M[i] = lrelu(g_AS[i] + g_AD[i]);
}

// edge segment max. one thread per edge.
__global__ void emax_kernel(const int* __restrict__ src, const int* __restrict__ dst,
                            const int* __restrict__ etype, int r) {
    int e = blockIdx.x * blockDim.x + threadIdx.x;
    if (e >= NEDGE || etype[e] != r) return;
    int s = src[e], t = dst[e];
    #pragma unroll
    for (int gh = 0; gh < GHEADS; gh++) {
        float v = lrelu(g_AS[s * GHEADS + gh] + g_AD[t * GHEADS + gh]);
        atomicMaxF(&g_M[t * GHEADS + gh], v);
    }
}

// init NUM/DEN with self-loop term. grid NN, block 256.
__global__ void ninit_kernel() {
    int n = blockIdx.x, d = threadIdx.x;
    #pragma unroll
    for (int gh = 0; gh < GHEADS; gh++) {
        float es = lrelu(g_AS[n * GHEADS + gh] + g_AD[n * GHEADS + gh]);
        float ws = expf(es - g_M[n * GHEADS + gh]);
        g_NUM[(size_t)n * GHEADS * DIM + gh * DIM + d] =
            ws * g_XG[(size_t)n * GHEADS * DIM + gh * DIM + d];
        if (d == 0) g_DEN[n * GHEADS + gh] = ws;
    }
}

// edge accumulation. one block (256 thr) per edge: 4 heads x 256 dims.
__global__ void eacc_kernel(const int* __restrict__ src, const int* __restrict__ dst,
                            const int* __restrict__ etype, int r) {
    int e = blockIdx.x;
    if (etype[e] != r) return;
    int s = src[e], t = dst[e];
    int gh = threadIdx.x >> 6;
    int dd = threadIdx.x & 63;
    float w = expf(lrelu(g_AS[s * GHEADS + gh] + g_AD[t * GHEADS + gh])
                   - g_M[t * GHEADS + gh]);
    if (dd == 0) atomicAdd(&g_DEN[t * GHEADS + gh], w);
    const float* xs = g_XG + (size_t)s * GHEADS * DIM + gh * DIM;
    float* nm = g_NUM + (size_t)t * GHEADS * DIM + gh * DIM;
    #pragma unroll
    for (int k = 0; k < 4; k++) {
        int d = dd + 64 * k;
        atomicAdd(&nm[d], w * xs[d]);
    }
}

// h_new += mean_gh(num/den) + bias. grid NN, block 256.
__global__ void comb_kernel(const float* __restrict__ gb) {
    int n = blockIdx.x, d = threadIdx.x;
    float acc = 0.f;
    #pragma unroll
    for (int gh = 0; gh < GHEADS; gh++)
        acc += g_NUM[(size_t)n * GHEADS * DIM + gh * DIM + d] / g_DEN[n * GHEADS + gh];
    g_HN[(size_t)n * DIM + d] += acc * 0.25f + gb[d];
}

// h = relu(h + h_new). grid NN, block 256.
__global__ void hupd_kernel() {
    size_t i = (size_t)blockIdx.x * blockDim.x + threadIdx.x;
    g_H[i] = fmaxf(g_H[i] + g_HN[i], 0.f);
}

// final: tang = tanh(pos)*2*sqrt(exp(log_c)); Lorentz exp map. grid NN, block 256.
__global__ void final_kernel(const float* __restrict__ log_c, float* __restrict__ out) {
    int n = blockIdx.x, d = threadIdx.x;
    __shared__ float sh[256];
    __shared__ float stat;
    float scale = sqrtf(expf(log_c[0]));
    float st = tanhf(g_TH[(size_t)n * DIM + d]) * 2.f * scale;
    sh[d] = st * st; __syncthreads();
    for (int s = 128; s > 0; s >>= 1) { if (d < s) sh[d] += sh[d + s]; __syncthreads(); }
    if (d == 0) stat = sh[0];
    __syncthreads();
    float r = fmaxf(sqrtf(stat), 1e-8f);
    if (d == 0) out[(size_t)n * 257] = coshf(r);
    out[(size_t)n * 257 + 1 + d] = sinhf(r) / r * st;
}

// ---------------------------------------------------------------------------
// Host orchestration
// ---------------------------------------------------------------------------
extern "C" void kernel_launch(void* const* d_in, const int* in_sizes, int n_in,
                              void* d_out, int out_size) {
    const float* tok_emb = (const float*)d_in[0];
    const float* Wqkv    = (const float*)d_in[1];
    const float* bqkv    = (const float*)d_in[2];
    const float* Wo      = (const float*)d_in[3];
    const float* bo      = (const float*)d_in[4];
    const float* ln1g    = (const float*)d_in[5];
    const float* ln1b    = (const float*)d_in[6];
    const float* ln2g    = (const float*)d_in[7];
    const float* ln2b    = (const float*)d_in[8];
    const float* W1      = (const float*)d_in[9];
    const float* b1      = (const float*)d_in[10];
    const float* W2      = (const float*)d_in[11];
    const float* b2      = (const float*)d_in[12];
    const float* type_emb= (const float*)d_in[13];
    const float* msg_W   = (const float*)d_in[14];
    const float* msg_b   = (const float*)d_in[15];
    const float* gat_W   = (const float*)d_in[16];
    const float* gat_b   = (const float*)d_in[17];
    const float* asrc    = (const float*)d_in[18];
    const float* adst    = (const float*)d_in[19];
    const float* spW1    = (const float*)d_in[20];
    const float* spb1    = (const float*)d_in[21];
    const float* spW2    = (const float*)d_in[22];
    const float* spb2    = (const float*)d_in[23];
    const float* log_c   = (const float*)d_in[24];
    const int*   tokens  = (const int*)d_in[25];
    const int*   types   = (const int*)d_in[26];
    const int*   eidx    = (const int*)d_in[27];
    const int*   etype   = (const int*)d_in[28];
    const int* esrc = eidx;
    const int* edst = eidx + NEDGE;
    float* out = (float*)d_out;

    float *pX, *pQKV, *pT1, *pT2, *pH, *pHN, *pTH, *pXG, *pSPH;
    cudaGetSymbolAddress((void**)&pX,   g_X);
    cudaGetSymbolAddress((void**)&pQKV, g_QKV);
    cudaGetSymbolAddress((void**)&pT1,  g_T1);
    cudaGetSymbolAddress((void**)&pT2,  g_T2);
    cudaGetSymbolAddress((void**)&pH,   g_H);
    cudaGetSymbolAddress((void**)&pHN,  g_HN);
    cudaGetSymbolAddress((void**)&pTH,  g_TH);
    cudaGetSymbolAddress((void**)&pXG,  g_XG);
    cudaGetSymbolAddress((void**)&pSPH, g_SPH);

    // 1) embedding + PE
    embed_kernel<<<NTOK, 256>>>(tok_emb, tokens);

    // 2) transformer encoder, 2 layers
    for (int l = 0; l < 2; l++) {
        gemm_kernel<<<dim3(3 * DIM / 64, NTOK / 64), 256>>>(
            pX, Wqkv + (size_t)l * DIM * 3 * DIM, bqkv + l * 3 * DIM, pQKV,
            NTOK, 3 * DIM, DIM, 0);
        attn_kernel<<<NN * NH, 64>>>();
        gemm_kernel<<<dim3(DIM / 64, NTOK / 64), 256>>>(
            pT1, Wo + (size_t)l * DIM * DIM, bo + l * DIM, pT2,
            NTOK, DIM, DIM, 0);
        add_ln_kernel<<<NTOK, 256>>>(pT2, ln1g + l * DIM, ln1b + l * DIM);
        gemm_kernel<<<dim3(DIM / 64, NTOK / 64), 256>>>(
            pX, W1 + (size_t)l * DIM * DIM, b1 + l * DIM, pT1,
            NTOK, DIM, DIM, 1);
        gemm_kernel<<<dim3(DIM / 64, NTOK / 64), 256>>>(
            pT1, W2 + (size_t)l * DIM * DIM, b2 + l * DIM, pT2,
            NTOK, DIM, DIM, 0);
        add_ln_kernel<<<NTOK, 256>>>(pT2, ln2g + l * DIM, ln2b + l * DIM);
    }

    // 3) mean over seq + type embedding
    mean_kernel<<<NN, 256>>>(types, type_emb);

    // 4) 4 GNN layers x 3 relations of GAT
    for (int l = 0; l < 4; l++) {
        cudaMemsetAsync(pHN, 0, NN * DIM * sizeof(float));
        for (int r = 0; r < 3; r++) {
            gemm_kernel<<<dim3(DIM / 64, NN / 64), 256>>>(
                pH, msg_W + (size_t)r * DIM * DIM, msg_b + r * DIM, pTH,
                NN, DIM, DIM, 0);
            gemm_kernel<<<dim3(GHEADS * DIM / 64, NN / 64), 256>>>(
                pTH, gat_W + (size_t)l * DIM * GHEADS * DIM, nullptr, pXG,
                NN, GHEADS * DIM, DIM, 0);
            asd_kernel<<<NN, 128>>>(asrc + l * GHEADS * DIM, adst + l * GHEADS * DIM);
            minit_kernel<<<(NN * GHEADS + 255) / 256, 256>>>();
            emax_kernel<<<(NEDGE + 127) / 128, 128>>>(esrc, edst, etype, r);
            ninit_kernel<<<NN, 256>>>();
            eacc_kernel<<<NEDGE, 256>>>(esrc, edst, etype, r);
            comb_kernel<<<NN, 256>>>(gat_b + l * DIM);
        }
        hupd_kernel<<<NN, 256>>>();
    }

    // 5) scoring MLP + Lorentz exp map
    gemm_kernel<<<dim3(SPH / 64, NN / 64), 256>>>(pH, spW1, spb1, pSPH, NN, SPH, DIM, 1);
    gemm_kernel<<<dim3(DIM / 64, NN / 64), 256>>>(pSPH, spW2, spb2, pTH, NN, DIM, SPH, 0);
    final_kernel<<<NN, 256>>>(log_c, out);
}

// round 3
// speedup vs baseline: 2.0175x; 2.0175x over previous
#include <cuda_runtime.h>
#include <cuda_bf16.h>
#include <math.h>
#include <stdint.h>

// ---------------------------------------------------------------------------
// Problem constants
// ---------------------------------------------------------------------------
#define NN      2048
#define SEQ     64
#define DIM     256
#define NH      8
#define DH      32
#define GHEADS  4
#define NEDGE   32768
#define NTOK    (NN*SEQ)
#define SPH     512

// ---------------------------------------------------------------------------
// Scratch (device globals)
// ---------------------------------------------------------------------------
__device__ float g_X  [NTOK*DIM];
__device__ float g_QKV[NTOK*3*DIM];
__device__ float g_T1 [NTOK*DIM];
__device__ float g_T2 [NTOK*DIM];
__device__ float g_H  [NN*DIM];
__device__ float g_HN [NN*DIM];
__device__ float g_TH [NN*DIM];
__device__ float g_THA[NN*3*DIM];        // fused msg output [2048, 768]
__device__ float g_XG [NN*GHEADS*DIM];
__device__ float g_AS [NN*GHEADS];
__device__ float g_AD [NN*GHEADS];
__device__ float g_M  [NN*GHEADS];
__device__ float g_DEN[NN*GHEADS];
__device__ float g_NUM[NN*GHEADS*DIM];
__device__ float g_SPH[NN*SPH];

// transposed weights, K-major [N, K]
#define WT_QKV   0                       // 2 x 768x256
#define WT_WO    (WT_QKV + 2*768*256)    // 2 x 256x256
#define WT_W1    (WT_WO  + 2*256*256)
#define WT_W2    (WT_W1  + 2*256*256)
#define WT_MSG   (WT_W2  + 2*256*256)    // 3 x 256x256 contiguous = 768x256
#define WT_GAT   (WT_MSG + 3*256*256)    // 4 x 1024x256
#define WT_SP1   (WT_GAT + 4*1024*256)   // 512x256
#define WT_SP2   (WT_SP1 + 512*256)      // 256x512
#define WT_TOTAL (WT_SP2 + 256*512)
__device__ float g_WT[WT_TOTAL];

// ---------------------------------------------------------------------------
// Helpers
// ---------------------------------------------------------------------------
__device__ __forceinline__ float lrelu(float x) { return x > 0.f ? x : 0.2f * x; }

__device__ __forceinline__ void atomicMaxF(float* addr, float v) {
    if (v >= 0.f) atomicMax((int*)addr, __float_as_int(v));
    else          atomicMin((unsigned int*)addr, __float_as_uint(v));
}

__device__ __forceinline__ uint32_t smem_u32(const void* p) {
    uint32_t a;
    asm("{ .reg .u64 t; cvta.to.shared.u64 t, %1; cvt.u32.u64 %0, t; }" : "=r"(a) : "l"(p));
    return a;
}

// split fp32 pair into bf16-hi pair and bf16-lo (residual) pair, packed
__device__ __forceinline__ void split2(float a, float b, uint32_t& hi, uint32_t& lo) {
    __nv_bfloat16 ha = __float2bfloat16_rn(a), hb = __float2bfloat16_rn(b);
    float ra = a - __bfloat162float(ha);
    float rb = b - __bfloat162float(hb);
    __nv_bfloat16 la = __float2bfloat16_rn(ra), lb = __float2bfloat16_rn(rb);
    hi = (uint32_t)__bfloat16_as_ushort(ha) | ((uint32_t)__bfloat16_as_ushort(hb) << 16);
    lo = (uint32_t)__bfloat16_as_ushort(la) | ((uint32_t)__bfloat16_as_ushort(lb) << 16);
}

__device__ __forceinline__ void ldsm_x4(uint32_t* r, uint32_t a) {
    asm volatile("ldmatrix.sync.aligned.m8n8.x4.shared.b16 {%0,%1,%2,%3}, [%4];"
                 : "=r"(r[0]), "=r"(r[1]), "=r"(r[2]), "=r"(r[3]) : "r"(a));
}
__device__ __forceinline__ void ldsm_x2(uint32_t* r, uint32_t a) {
    asm volatile("ldmatrix.sync.aligned.m8n8.x2.shared.b16 {%0,%1}, [%2];"
                 : "=r"(r[0]), "=r"(r[1]) : "r"(a));
}

__device__ __forceinline__ void mma16816(float* c, const uint32_t* a, const uint32_t* b) {
    asm volatile(
        "mma.sync.aligned.m16n8k16.row.col.f32.bf16.bf16.f32 "
        "{%0,%1,%2,%3}, {%4,%5,%6,%7}, {%8,%9}, {%0,%1,%2,%3};"
        : "+f"(c[0]), "+f"(c[1]), "+f"(c[2]), "+f"(c[3])
        : "r"(a[0]), "r"(a[1]), "r"(a[2]), "r"(a[3]), "r"(b[0]), "r"(b[1]));
}

// ---------------------------------------------------------------------------
// bf16-split mma.sync GEMM: C[M,N] = A[M,K](lda) @ BT[N,K]^T (+bias)(+relu)
// CTA tile 128x128, 8 warps (warp tile 32x64), K-chunks of 32.
// Static smem 32KB: aHi/aLo/bHi/bLo, each 128 rows x 32 halves, swizzled.
// Requirements: M%128==0, N%128==0, K%32==0, pointers 16B aligned.
// ---------------------------------------------------------------------------
#define TILE_HALF_BYTES 8192   // 128*32*2

__global__ void __launch_bounds__(256)
gemm_mma(const float* __restrict__ A, int lda,
         const float* __restrict__ BT,
         const float* __restrict__ bias,
         float* __restrict__ C, int M, int N, int K, int act) {
    __shared__ char sm[4 * TILE_HALF_BYTES];
    const uint32_t sb = smem_u32(sm);
    const int tid  = threadIdx.x;
    const int lane = tid & 31;
    const int warp = tid >> 5;
    const int wm = warp & 3;          // 4 warps along M
    const int wn = warp >> 2;         // 2 warps along N
    const int row0 = blockIdx.y * 128;
    const int col0 = blockIdx.x * 128;

    float acc[2][8][4];
    #pragma unroll
    for (int i = 0; i < 2; i++)
        #pragma unroll
        for (int j = 0; j < 8; j++)
            #pragma unroll
            for (int k = 0; k < 4; k++) acc[i][j][k] = 0.f;

    // swizzled 16B-chunk offset: element (r, chunk c of 4) -> (r*4 + (c ^ ((r>>1)&3)))*16
    const int nch = K >> 5;
    for (int ch = 0; ch < nch; ch++) {
        if (ch) __syncthreads();
        const int k0 = ch << 5;
        // load A chunk 128x32 and B chunk 128x32 (4 float4 each per thread)
        #pragma unroll
        for (int i = 0; i < 4; i++) {
            int idx = tid + i * 256;           // 0..1023
            int r = idx >> 3, g = idx & 7;     // g: float4 index (4 halves)
            uint32_t h0, l0, h1, l1;
            float4 v = *(const float4*)(A + (size_t)(row0 + r) * lda + k0 + g * 4);
            split2(v.x, v.y, h0, l0);
            split2(v.z, v.w, h1, l1);
            uint32_t off = (uint32_t)(r * 4 + ((g >> 1) ^ ((r >> 1) & 3))) * 16 + (g & 1) * 8;
            *(uint2*)(sm + off)                    = make_uint2(h0, h1);
            *(uint2*)(sm + TILE_HALF_BYTES + off)  = make_uint2(l0, l1);
        }
        #pragma unroll
        for (int i = 0; i < 4; i++) {
            int idx = tid + i * 256;
            int r = idx >> 3, g = idx & 7;
            uint32_t h0, l0, h1, l1;
            float4 v = *(const float4*)(BT + (size_t)(col0 + r) * K + k0 + g * 4);
            split2(v.x, v.y, h0, l0);
            split2(v.z, v.w, h1, l1);
            uint32_t off = (uint32_t)(r * 4 + ((g >> 1) ^ ((r >> 1) & 3))) * 16 + (g & 1) * 8;
            *(uint2*)(sm + 2 * TILE_HALF_BYTES + off) = make_uint2(h0, h1);
            *(uint2*)(sm + 3 * TILE_HALF_BYTES + off) = make_uint2(l0, l1);
        }
        __syncthreads();

        #pragma unroll
        for (int s = 0; s < 2; s++) {          // two k16 steps per 32-chunk
            uint32_t ah[2][4], al[2][4];
            #pragma unroll
            for (int mt = 0; mt < 2; mt++) {
                int row = wm * 32 + mt * 16 + (lane & 15);
                int c = 2 * s + (lane >> 4);
                uint32_t off = (uint32_t)(row * 4 + (c ^ ((row >> 1) & 3))) * 16;
                ldsm_x4(ah[mt], sb + off);
                ldsm_x4(al[mt], sb + TILE_HALF_BYTES + off);
            }
            #pragma unroll
            for (int nt = 0; nt < 8; nt++) {
                int nr = wn * 64 + nt * 8 + (lane & 7);
                int c = 2 * s + ((lane >> 3) & 1);
                uint32_t off = (uint32_t)(nr * 4 + (c ^ ((nr >> 1) & 3))) * 16;
                uint32_t bh[2], bl[2];
                ldsm_x2(bh, sb + 2 * TILE_HALF_BYTES + off);
                ldsm_x2(bl, sb + 3 * TILE_HALF_BYTES + off);
                #pragma unroll
                for (int mt = 0; mt < 2; mt++) {
                    mma16816(acc[mt][nt], ah[mt], bh);
                    mma16816(acc[mt][nt], ah[mt], bl);
                    mma16816(acc[mt][nt], al[mt], bh);
                }
            }
        }
    }

    // epilogue
    const int g4 = lane >> 2, tig = lane & 3;
    #pragma unroll
    for (int nt = 0; nt < 8; nt++) {
        int col = col0 + wn * 64 + nt * 8 + tig * 2;
        float b0 = 0.f, b1 = 0.f;
        if (bias) { b0 = bias[col]; b1 = bias[col + 1]; }
        #pragma unroll
        for (int mt = 0; mt < 2; mt++) {
            int row = row0 + wm * 32 + mt * 16 + g4;
            float v0 = acc[mt][nt][0] + b0;
            float v1 = acc[mt][nt][1] + b1;
            float v2 = acc[mt][nt][2] + b0;
            float v3 = acc[mt][nt][3] + b1;
            if (act) {
                v0 = fmaxf(v0, 0.f); v1 = fmaxf(v1, 0.f);
                v2 = fmaxf(v2, 0.f); v3 = fmaxf(v3, 0.f);
            }
            *(float2*)(C + (size_t)row * N + col)       = make_float2(v0, v1);
            *(float2*)(C + (size_t)(row + 8) * N + col) = make_float2(v2, v3);
        }
    }
}

// ---------------------------------------------------------------------------
// Weight transpose: B[K,N] -> BT[N,K]
// ---------------------------------------------------------------------------
__global__ void transpose_kernel(const float* __restrict__ B, float* __restrict__ BT,
                                 int K, int N) {
    __shared__ float t[32][33];
    int n0 = blockIdx.x * 32, k0 = blockIdx.y * 32;
    int x = threadIdx.x, y = threadIdx.y;
    #pragma unroll
    for (int i = 0; i < 4; i++)
        t[y + i * 8][x] = B[(size_t)(k0 + y + i * 8) * N + n0 + x];
    __syncthreads();
    #pragma unroll
    for (int i = 0; i < 4; i++)
        BT[(size_t)(n0 + y + i * 8) * K + k0 + x] = t[x][y + i * 8];
}

// ---------------------------------------------------------------------------
// Elementwise / reduction kernels
// ---------------------------------------------------------------------------
__global__ void embed_kernel(const float* __restrict__ tok_emb,
                             const int* __restrict__ tokens) {
    int row = blockIdx.x;
    int s = row & (SEQ - 1);
    int d = threadIdx.x;
    int tok = tokens[row];
    int i2 = d >> 1;
    float div = expf((float)(2 * i2) * (-logf(10000.f) / (float)DIM));
    float arg = (float)s * div;
    float pe = (d & 1) ? cosf(arg) : sinf(arg);
    g_X[(size_t)row * DIM + d] = tok_emb[(size_t)tok * DIM + d] * 16.f + pe;
}

__global__ void attn_kernel() {
    int n = blockIdx.x >> 3;
    int h = blockIdx.x & 7;
    __shared__ float Qs[SEQ][DH + 1];
    __shared__ float Ks[SEQ][DH + 1];
    __shared__ float Vs[SEQ][DH + 1];
    const float* base = g_QKV + (size_t)n * SEQ * 3 * DIM;
    for (int e = threadIdx.x; e < SEQ * DH; e += blockDim.x) {
        int r = e >> 5, d = e & 31;
        Qs[r][d] = base[r * 3 * DIM + h * DH + d];
        Ks[r][d] = base[r * 3 * DIM + DIM + h * DH + d];
        Vs[r][d] = base[r * 3 * DIM + 2 * DIM + h * DH + d];
    }
    __syncthreads();
    int i = threadIdx.x;
    float q[DH];
    #pragma unroll
    for (int d = 0; d < DH; d++) q[d] = Qs[i][d];
    const float scale = 0.17677669529663687f;
    float m = -1e30f, l = 0.f;
    float o[DH];
    #pragma unroll
    for (int d = 0; d < DH; d++) o[d] = 0.f;
    for (int j = 0; j < SEQ; j++) {
        float s = 0.f;
        #pragma unroll
        for (int d = 0; d < DH; d++) s += q[d] * Ks[j][d];
        s *= scale;
        if (s > m) {
            float c = expf(m - s);
            l *= c;
            #pragma unroll
            for (int d = 0; d < DH; d++) o[d] *= c;
            m = s;
        }
        float p = expf(s - m);
        l += p;
        #pragma unroll
        for (int d = 0; d < DH; d++) o[d] += p * Vs[j][d];
    }
    float inv = 1.f / l;
    float* out = g_T1 + ((size_t)n * SEQ + i) * DIM + h * DH;
    #pragma unroll
    for (int d = 0; d < DH; d++) out[d] = o[d] * inv;
}

__global__ void add_ln_kernel(const float* __restrict__ T,
                              const float* __restrict__ g,
                              const float* __restrict__ b) {
    int row = blockIdx.x;
    int d = threadIdx.x;
    __shared__ float sh[256];
    __shared__ float stat;
    float v = g_X[(size_t)row * DIM + d] + T[(size_t)row * DIM + d];
    sh[d] = v; __syncthreads();
    for (int s = 128; s > 0; s >>= 1) { if (d < s) sh[d] += sh[d + s]; __syncthreads(); }
    if (d == 0) stat = sh[0] * (1.f / 256.f);
    __syncthreads();
    float mean = stat;
    float diff = v - mean;
    __syncthreads();
    sh[d] = diff * diff; __syncthreads();
    for (int s = 128; s > 0; s >>= 1) { if (d < s) sh[d] += sh[d + s]; __syncthreads(); }
    if (d == 0) stat = sh[0] * (1.f / 256.f);
    __syncthreads();
    float var = stat;
    g_X[(size_t)row * DIM + d] = diff * rsqrtf(var + 1e-5f) * g[d] + b[d];
}

__global__ void mean_kernel(const int* __restrict__ types,
                            const float* __restrict__ type_emb) {
    int n = blockIdx.x, d = threadIdx.x;
    float acc = 0.f;
    const float* base = g_X + (size_t)n * SEQ * DIM + d;
    for (int s = 0; s < SEQ; s++) acc += base[s * DIM];
    g_H[(size_t)n * DIM + d] = acc * (1.f / SEQ) + type_emb[(size_t)types[n] * DIM + d];
}

__global__ void asd_kernel(const float* __restrict__ asrc,
                           const float* __restrict__ adst) {
    int n = blockIdx.x;
    int w = threadIdx.x >> 5, lane = threadIdx.x & 31;
    float s1 = 0.f, s2 = 0.f;
    const float* xg = g_XG + (size_t)n * GHEADS * DIM + w * DIM;
    #pragma unroll
    for (int d = lane; d < DIM; d += 32) {
        float xv = xg[d];
        s1 += xv * asrc[w * DIM + d];
        s2 += xv * adst[w * DIM + d];
    }
    #pragma unroll
    for (int off = 16; off > 0; off >>= 1) {
        s1 += __shfl_down_sync(0xffffffffu, s1, off);
        s2 += __shfl_down_sync(0xffffffffu, s2, off);
    }
    if (lane == 0) {
        g_AS[n * GHEADS + w] = s1;
        g_AD[n * GHEADS + w] = s2;
    }
}

__global__ void minit_kernel() {
    int i = blockIdx.x * blockDim.x + threadIdx.x;
    if (i >= NN * GHEADS) return;
    g_M[i] = lrelu(g_AS[i] + g_AD[i]);
}

__global__ void emax_kernel(const int* __restrict__ src, const int* __restrict__ dst,
                            const int* __restrict__ etype, int r) {
    int e = blockIdx.x * blockDim.x + threadIdx.x;
    if (e >= NEDGE || etype[e] != r) return;
    int s = src[e], t = dst[e];
    #pragma unroll
    for (int gh = 0; gh < GHEADS; gh++) {
        float v = lrelu(g_AS[s * GHEADS + gh] + g_AD[t * GHEADS + gh]);
        atomicMaxF(&g_M[t * GHEADS + gh], v);
    }
}

__global__ void ninit_kernel() {
    int n = blockIdx.x, d = threadIdx.x;
    #pragma unroll
    for (int gh = 0; gh < GHEADS; gh++) {
        float es = lrelu(g_AS[n * GHEADS + gh] + g_AD[n * GHEADS + gh]);
        float ws = expf(es - g_M[n * GHEADS + gh]);
        g_NUM[(size_t)n * GHEADS * DIM + gh * DIM + d] =
            ws * g_XG[(size_t)n * GHEADS * DIM + gh * DIM + d];
        if (d == 0) g_DEN[n * GHEADS + gh] = ws;
    }
}

__global__ void eacc_kernel(const int* __restrict__ src, const int* __restrict__ dst,
                            const int* __restrict__ etype, int r) {
    int e = blockIdx.x;
    if (etype[e] != r) return;
    int s = src[e], t = dst[e];
    int gh = threadIdx.x >> 6;
    int dd = threadIdx.x & 63;
    float w = expf(lrelu(g_AS[s * GHEADS + gh] + g_AD[t * GHEADS + gh])
                   - g_M[t * GHEADS + gh]);
    if (dd == 0) atomicAdd(&g_DEN[t * GHEADS + gh], w);
    const float* xs = g_XG + (size_t)s * GHEADS * DIM + gh * DIM;
    float* nm = g_NUM + (size_t)t * GHEADS * DIM + gh * DIM;
    #pragma unroll
    for (int k = 0; k < 4; k++) {
        int d = dd + 64 * k;
        atomicAdd(&nm[d], w * xs[d]);
    }
}

__global__ void comb_kernel(const float* __restrict__ gb) {
    int n = blockIdx.x, d = threadIdx.x;
    float acc = 0.f;
    #pragma unroll
    for (int gh = 0; gh < GHEADS; gh++)
        acc += g_NUM[(size_t)n * GHEADS * DIM + gh * DIM + d] / g_DEN[n * GHEADS + gh];
    g_HN[(size_t)n * DIM + d] += acc * 0.25f + gb[d];
}

__global__ void hupd_kernel() {
    size_t i = (size_t)blockIdx.x * blockDim.x + threadIdx.x;
    g_H[i] = fmaxf(g_H[i] + g_HN[i], 0.f);
}

__global__ void final_kernel(const float* __restrict__ log_c, float* __restrict__ out) {
    int n = blockIdx.x, d = threadIdx.x;
    __shared__ float sh[256];
    __shared__ float stat;
    float scale = sqrtf(expf(log_c[0]));
    float st = tanhf(g_TH[(size_t)n * DIM + d]) * 2.f * scale;
    sh[d] = st * st; __syncthreads();
    for (int s = 128; s > 0; s >>= 1) { if (d < s) sh[d] += sh[d + s]; __syncthreads(); }
    if (d == 0) stat = sh[0];
    __syncthreads();
    float r = fmaxf(sqrtf(stat), 1e-8f);
    if (d == 0) out[(size_t)n * 257] = coshf(r);
    out[(size_t)n * 257 + 1 + d] = sinhf(r) / r * st;
}

// ---------------------------------------------------------------------------
// Host orchestration
// ---------------------------------------------------------------------------
extern "C" void kernel_launch(void* const* d_in, const int* in_sizes, int n_in,
                              void* d_out, int out_size) {
    const float* tok_emb = (const float*)d_in[0];
    const float* Wqkv    = (const float*)d_in[1];
    const float* bqkv    = (const float*)d_in[2];
    const float* Wo      = (const float*)d_in[3];
    const float* bo      = (const float*)d_in[4];
    const float* ln1g    = (const float*)d_in[5];
    const float* ln1b    = (const float*)d_in[6];
    const float* ln2g    = (const float*)d_in[7];
    const float* ln2b    = (const float*)d_in[8];
    const float* W1      = (const float*)d_in[9];
    const float* b1      = (const float*)d_in[10];
    const float* W2      = (const float*)d_in[11];
    const float* b2      = (const float*)d_in[12];
    const float* type_emb= (const float*)d_in[13];
    const float* msg_W   = (const float*)d_in[14];
    const float* msg_b   = (const float*)d_in[15];
    const float* gat_W   = (const float*)d_in[16];
    const float* gat_b   = (const float*)d_in[17];
    const float* asrc    = (const float*)d_in[18];
    const float* adst    = (const float*)d_in[19];
    const float* spW1    = (const float*)d_in[20];
    const float* spb1    = (const float*)d_in[21];
    const float* spW2    = (const float*)d_in[22];
    const float* spb2    = (const float*)d_in[23];
    const float* log_c   = (const float*)d_in[24];
    const int*   tokens  = (const int*)d_in[25];
    const int*   types   = (const int*)d_in[26];
    const int*   eidx    = (const int*)d_in[27];
    const int*   etype   = (const int*)d_in[28];
    const int* esrc = eidx;
    const int* edst = eidx + NEDGE;
    float* out = (float*)d_out;

    float *pX, *pQKV, *pT1, *pT2, *pH, *pHN, *pTH, *pTHA, *pXG, *pSPH, *pWT;
    cudaGetSymbolAddress((void**)&pX,   g_X);
    cudaGetSymbolAddress((void**)&pQKV, g_QKV);
    cudaGetSymbolAddress((void**)&pT1,  g_T1);
    cudaGetSymbolAddress((void**)&pT2,  g_T2);
    cudaGetSymbolAddress((void**)&pH,   g_H);
    cudaGetSymbolAddress((void**)&pHN,  g_HN);
    cudaGetSymbolAddress((void**)&pTH,  g_TH);
    cudaGetSymbolAddress((void**)&pTHA, g_THA);
    cudaGetSymbolAddress((void**)&pXG,  g_XG);
    cudaGetSymbolAddress((void**)&pSPH, g_SPH);
    cudaGetSymbolAddress((void**)&pWT,  g_WT);

    // 0) transpose all weights to K-major
    {
        dim3 blk(32, 8);
        for (int l = 0; l < 2; l++) {
            transpose_kernel<<<dim3(768 / 32, 256 / 32), blk>>>(Wqkv + (size_t)l * 256 * 768, pWT + WT_QKV + l * 768 * 256, 256, 768);
            transpose_kernel<<<dim3(8, 8), blk>>>(Wo + (size_t)l * 65536, pWT + WT_WO + l * 65536, 256, 256);
            transpose_kernel<<<dim3(8, 8), blk>>>(W1 + (size_t)l * 65536, pWT + WT_W1 + l * 65536, 256, 256);
            transpose_kernel<<<dim3(8, 8), blk>>>(W2 + (size_t)l * 65536, pWT + WT_W2 + l * 65536, 256, 256);
        }
        for (int r = 0; r < 3; r++)
            transpose_kernel<<<dim3(8, 8), blk>>>(msg_W + (size_t)r * 65536, pWT + WT_MSG + r * 65536, 256, 256);
        for (int l = 0; l < 4; l++)
            transpose_kernel<<<dim3(1024 / 32, 8), blk>>>(gat_W + (size_t)l * 256 * 1024, pWT + WT_GAT + l * 1024 * 256, 256, 1024);
        transpose_kernel<<<dim3(512 / 32, 8), blk>>>(spW1, pWT + WT_SP1, 256, 512);
        transpose_kernel<<<dim3(8, 512 / 32), blk>>>(spW2, pWT + WT_SP2, 512, 256);
    }

    // 1) embedding + PE
    embed_kernel<<<NTOK, 256>>>(tok_emb, tokens);

    // 2) transformer encoder
    for (int l = 0; l < 2; l++) {
        gemm_mma<<<dim3(6, NTOK / 128), 256>>>(
            pX, 256, pWT + WT_QKV + l * 768 * 256, bqkv + l * 768, pQKV,
            NTOK, 768, 256, 0);
        attn_kernel<<<NN * NH, 64>>>();
        gemm_mma<<<dim3(2, NTOK / 128), 256>>>(
            pT1, 256, pWT + WT_WO + l * 65536, bo + l * 256, pT2,
            NTOK, 256, 256, 0);
        add_ln_kernel<<<NTOK, 256>>>(pT2, ln1g + l * 256, ln1b + l * 256);
        gemm_mma<<<dim3(2, NTOK / 128), 256>>>(
            pX, 256, pWT + WT_W1 + l * 65536, b1 + l * 256, pT1,
            NTOK, 256, 256, 1);
        gemm_mma<<<dim3(2, NTOK / 128), 256>>>(
            pT1, 256, pWT + WT_W2 + l * 65536, b2 + l * 256, pT2,
            NTOK, 256, 256, 0);
        add_ln_kernel<<<NTOK, 256>>>(pT2, ln2g + l * 256, ln2b + l * 256);
    }

    // 3) mean over seq + type embedding
    mean_kernel<<<NN, 256>>>(types, type_emb);

    // 4) 4 GNN layers
    for (int l = 0; l < 4; l++) {
        cudaMemsetAsync(pHN, 0, NN * DIM * sizeof(float));
        // fused per-relation msg GEMM: th_all[2048,768] = h @ [W0|W1|W2] + [b0|b1|b2]
        gemm_mma<<<dim3(6, NN / 128), 256>>>(
            pH, 256, pWT + WT_MSG, msg_b, pTHA, NN, 768, 256, 0);
        for (int r = 0; r < 3; r++) {
            gemm_mma<<<dim3(8, NN / 128), 256>>>(
                pTHA + r * 256, 768, pWT + WT_GAT + l * 1024 * 256, nullptr, pXG,
                NN, 1024, 256, 0);
            asd_kernel<<<NN, 128>>>(asrc + l * GHEADS * DIM, adst + l * GHEADS * DIM);
            minit_kernel<<<(NN * GHEADS + 255) / 256, 256>>>();
            emax_kernel<<<(NEDGE + 127) / 128, 128>>>(esrc, edst, etype, r);
            ninit_kernel<<<NN, 256>>>();
            eacc_kernel<<<NEDGE, 256>>>(esrc, edst, etype, r);
            comb_kernel<<<NN, 256>>>(gat_b + l * 256);
        }
        hupd_kernel<<<NN, 256>>>();
    }

    // 5) scoring MLP + Lorentz exp map
    gemm_mma<<<dim3(4, NN / 128), 256>>>(pH, 256, pWT + WT_SP1, spb1, pSPH, NN, 512, 256, 1);
    gemm_mma<<<dim3(2, NN / 128), 256>>>(pSPH, 512, pWT + WT_SP2, spb2, pTH, NN, 256, 512, 0);
    final_kernel<<<NN, 256>>>(log_c, out);
}

// round 4
// speedup vs baseline: 2.1348x; 1.0582x over previous
#include <cuda_runtime.h>
#include <cuda_bf16.h>
#include <math.h>
#include <stdint.h>

// ---------------------------------------------------------------------------
// Problem constants
// ---------------------------------------------------------------------------
#define NN      2048
#define SEQ     64
#define DIM     256
#define NH      8
#define DH      32
#define GHEADS  4
#define NEDGE   32768
#define NTOK    (NN*SEQ)
#define SPH     512

// ---------------------------------------------------------------------------
// Scratch (device globals)
// ---------------------------------------------------------------------------
__device__ float g_X  [NTOK*DIM];
__device__ float g_QKV[NTOK*3*DIM];
__device__ float g_T2 [NTOK*DIM];
__device__ float g_H  [NN*DIM];
__device__ float g_HN [NN*DIM];
__device__ float g_TH [NN*DIM];
__device__ float g_XG [NN*GHEADS*DIM];
__device__ float g_AS [NN*GHEADS];
__device__ float g_AD [NN*GHEADS];
__device__ float g_M  [NN*GHEADS];
__device__ float g_DEN[NN*GHEADS];
__device__ float g_NUM[NN*GHEADS*DIM];

// bf16 hi/lo split activations
__device__ __nv_bfloat16 g_Xh [NTOK*DIM],  g_Xl [NTOK*DIM];
__device__ __nv_bfloat16 g_T1h[NTOK*DIM],  g_T1l[NTOK*DIM];
__device__ __nv_bfloat16 g_Hh [NN*DIM],    g_Hl [NN*DIM];
__device__ __nv_bfloat16 g_THAh[NN*3*DIM], g_THAl[NN*3*DIM];
__device__ __nv_bfloat16 g_SPHh[NN*SPH],   g_SPHl[NN*SPH];

// transposed + split weights, K-major [N, K]
#define WT_QKV   0
#define WT_WO    (WT_QKV + 2*768*256)
#define WT_W1    (WT_WO  + 2*256*256)
#define WT_W2    (WT_W1  + 2*256*256)
#define WT_MSG   (WT_W2  + 2*256*256)
#define WT_GAT   (WT_MSG + 3*256*256)
#define WT_SP1   (WT_GAT + 4*1024*256)
#define WT_SP2   (WT_SP1 + 512*256)
#define WT_TOTAL (WT_SP2 + 256*512)
__device__ __nv_bfloat16 g_WTh[WT_TOTAL], g_WTl[WT_TOTAL];

// ---------------------------------------------------------------------------
// Helpers
// ---------------------------------------------------------------------------
__device__ __forceinline__ float lrelu(float x) { return x > 0.f ? x : 0.2f * x; }

__device__ __forceinline__ void atomicMaxF(float* addr, float v) {
    if (v >= 0.f) atomicMax((int*)addr, __float_as_int(v));
    else          atomicMin((unsigned int*)addr, __float_as_uint(v));
}

__device__ __forceinline__ uint32_t smem_u32(const void* p) {
    uint32_t a;
    asm("{ .reg .u64 t; cvta.to.shared.u64 t, %1; cvt.u32.u64 %0, t; }" : "=r"(a) : "l"(p));
    return a;
}

__device__ __forceinline__ void split1(float v, __nv_bfloat16& h, __nv_bfloat16& l) {
    h = __float2bfloat16_rn(v);
    l = __float2bfloat16_rn(v - __bfloat162float(h));
}

__device__ __forceinline__ void split2(float a, float b, uint32_t& hi, uint32_t& lo) {
    __nv_bfloat16 ha, la, hb, lb;
    split1(a, ha, la);
    split1(b, hb, lb);
    hi = (uint32_t)__bfloat16_as_ushort(ha) | ((uint32_t)__bfloat16_as_ushort(hb) << 16);
    lo = (uint32_t)__bfloat16_as_ushort(la) | ((uint32_t)__bfloat16_as_ushort(lb) << 16);
}

__device__ __forceinline__ void ldsm_x4(uint32_t* r, uint32_t a) {
    asm volatile("ldmatrix.sync.aligned.m8n8.x4.shared.b16 {%0,%1,%2,%3}, [%4];"
                 : "=r"(r[0]), "=r"(r[1]), "=r"(r[2]), "=r"(r[3]) : "r"(a));
}
__device__ __forceinline__ void ldsm_x2(uint32_t* r, uint32_t a) {
    asm volatile("ldmatrix.sync.aligned.m8n8.x2.shared.b16 {%0,%1}, [%2];"
                 : "=r"(r[0]), "=r"(r[1]) : "r"(a));
}

__device__ __forceinline__ void mma16816(float* c, const uint32_t* a, const uint32_t* b) {
    asm volatile(
        "mma.sync.aligned.m16n8k16.row.col.f32.bf16.bf16.f32 "
        "{%0,%1,%2,%3}, {%4,%5,%6,%7}, {%8,%9}, {%0,%1,%2,%3};"
        : "+f"(c[0]), "+f"(c[1]), "+f"(c[2]), "+f"(c[3])
        : "r"(a[0]), "r"(a[1]), "r"(a[2]), "r"(a[3]), "r"(b[0]), "r"(b[1]));
}

__device__ __forceinline__ void cp_async16(uint32_t dst, const void* src) {
    asm volatile("cp.async.cg.shared.global [%0], [%1], 16;" :: "r"(dst), "l"(src) : "memory");
}
__device__ __forceinline__ void cp_commit() {
    asm volatile("cp.async.commit_group;" ::: "memory");
}
template<int W> __device__ __forceinline__ void cp_wait() {
    asm volatile("cp.async.wait_group %0;" :: "n"(W) : "memory");
}

// ---------------------------------------------------------------------------
// Pipelined bf16-split GEMM: C = A @ BT^T (+bias)(+relu)
// A given pre-split as (Ahi, Alo) [M, K] halves with row stride lda.
// BT pre-split as (Bhi, Blo) [N, K].
// CTA tile 128x128, 8 warps, KC=32, cp.async 2-stage, 64KB dyn smem.
// Outputs: optional fp32 Cf and/or split (Chi, Clo).
// ---------------------------------------------------------------------------
#define ARR_BYTES  8192        // 128 rows x 32 halves
#define STAGE_BYTES (4*ARR_BYTES)

__device__ __forceinline__ void gemm_issue(
    uint32_t sb, int stage, int tid,
    const __nv_bfloat16* Ahi, const __nv_bfloat16* Alo, int lda,
    const __nv_bfloat16* Bhi, const __nv_bfloat16* Blo, int K,
    int row0, int col0, int k0)
{
    #pragma unroll
    for (int i = 0; i < 8; i++) {
        int idx = tid + i * 256;          // 0..2047
        int arr = idx >> 9;               // 0..3
        int j   = idx & 511;
        int r   = j >> 2;
        int c   = j & 3;
        uint32_t dst = sb + stage * STAGE_BYTES + arr * ARR_BYTES
                     + (uint32_t)(r * 4 + (c ^ ((r >> 1) & 3))) * 16;
        const __nv_bfloat16* src;
        if (arr == 0)      src = Ahi + (size_t)(row0 + r) * lda + k0 + c * 8;
        else if (arr == 1) src = Alo + (size_t)(row0 + r) * lda + k0 + c * 8;
        else if (arr == 2) src = Bhi + (size_t)(col0 + r) * K + k0 + c * 8;
        else               src = Blo + (size_t)(col0 + r) * K + k0 + c * 8;
        cp_async16(dst, src);
    }
}

__global__ void __launch_bounds__(256)
gemm_bf16(const __nv_bfloat16* __restrict__ Ahi, const __nv_bfloat16* __restrict__ Alo, int lda,
          const __nv_bfloat16* __restrict__ Bhi, const __nv_bfloat16* __restrict__ Blo,
          const float* __restrict__ bias,
          float* __restrict__ Cf,
          __nv_bfloat16* __restrict__ Chi, __nv_bfloat16* __restrict__ Clo,
          int M, int N, int K, int act) {
    extern __shared__ char sm[];
    const uint32_t sb = smem_u32(sm);
    const int tid  = threadIdx.x;
    const int lane = tid & 31;
    const int warp = tid >> 5;
    const int wm = warp & 3;
    const int wn = warp >> 2;
    const int row0 = blockIdx.y * 128;
    const int col0 = blockIdx.x * 128;

    float acc[2][8][4];
    #pragma unroll
    for (int i = 0; i < 2; i++)
        #pragma unroll
        for (int j = 0; j < 8; j++)
            #pragma unroll
            for (int k = 0; k < 4; k++) acc[i][j][k] = 0.f;

    const int nch = K >> 5;
    gemm_issue(sb, 0, tid, Ahi, Alo, lda, Bhi, Blo, K, row0, col0, 0);
    cp_commit();

    for (int ch = 0; ch < nch; ch++) {
        if (ch + 1 < nch) {
            gemm_issue(sb, (ch + 1) & 1, tid, Ahi, Alo, lda, Bhi, Blo, K,
                       row0, col0, (ch + 1) << 5);
            cp_commit();
            cp_wait<1>();
        } else {
            cp_wait<0>();
        }
        __syncthreads();

        const uint32_t base = sb + (ch & 1) * STAGE_BYTES;
        #pragma unroll
        for (int s = 0; s < 2; s++) {
            uint32_t ah[2][4], al[2][4];
            #pragma unroll
            for (int mt = 0; mt < 2; mt++) {
                int row = wm * 32 + mt * 16 + (lane & 15);
                int c = 2 * s + (lane >> 4);
                uint32_t off = (uint32_t)(row * 4 + (c ^ ((row >> 1) & 3))) * 16;
                ldsm_x4(ah[mt], base + off);
                ldsm_x4(al[mt], base + ARR_BYTES + off);
            }
            #pragma unroll
            for (int nt = 0; nt < 8; nt++) {
                int nr = wn * 64 + nt * 8 + (lane & 7);
                int c = 2 * s + ((lane >> 3) & 1);
                uint32_t off = (uint32_t)(nr * 4 + (c ^ ((nr >> 1) & 3))) * 16;
                uint32_t bh[2], bl[2];
                ldsm_x2(bh, base + 2 * ARR_BYTES + off);
                ldsm_x2(bl, base + 3 * ARR_BYTES + off);
                #pragma unroll
                for (int mt = 0; mt < 2; mt++) {
                    mma16816(acc[mt][nt], ah[mt], bh);
                    mma16816(acc[mt][nt], ah[mt], bl);
                    mma16816(acc[mt][nt], al[mt], bh);
                }
            }
        }
        __syncthreads();
    }

    // epilogue
    const int g4 = lane >> 2, tig = lane & 3;
    #pragma unroll
    for (int nt = 0; nt < 8; nt++) {
        int col = col0 + wn * 64 + nt * 8 + tig * 2;
        float b0 = 0.f, b1 = 0.f;
        if (bias) { b0 = bias[col]; b1 = bias[col + 1]; }
        #pragma unroll
        for (int mt = 0; mt < 2; mt++) {
            int row = row0 + wm * 32 + mt * 16 + g4;
            float v0 = acc[mt][nt][0] + b0;
            float v1 = acc[mt][nt][1] + b1;
            float v2 = acc[mt][nt][2] + b0;
            float v3 = acc[mt][nt][3] + b1;
            if (act) {
                v0 = fmaxf(v0, 0.f); v1 = fmaxf(v1, 0.f);
                v2 = fmaxf(v2, 0.f); v3 = fmaxf(v3, 0.f);
            }
            if (Cf) {
                *(float2*)(Cf + (size_t)row * N + col)       = make_float2(v0, v1);
                *(float2*)(Cf + (size_t)(row + 8) * N + col) = make_float2(v2, v3);
            }
            if (Chi) {
                uint32_t h01, l01, h23, l23;
                split2(v0, v1, h01, l01);
                split2(v2, v3, h23, l23);
                *(uint32_t*)(Chi + (size_t)row * N + col)       = h01;
                *(uint32_t*)(Clo + (size_t)row * N + col)       = l01;
                *(uint32_t*)(Chi + (size_t)(row + 8) * N + col) = h23;
                *(uint32_t*)(Clo + (size_t)(row + 8) * N + col) = l23;
            }
        }
    }
}

// ---------------------------------------------------------------------------
// Weight transpose + split: B[K,N] fp32 -> (Thi, Tlo)[N,K] bf16
// ---------------------------------------------------------------------------
__global__ void transpose_split(const float* __restrict__ B,
                                __nv_bfloat16* __restrict__ Thi,
                                __nv_bfloat16* __restrict__ Tlo,
                                int K, int N) {
    __shared__ float t[32][33];
    int n0 = blockIdx.x * 32, k0 = blockIdx.y * 32;
    int x = threadIdx.x, y = threadIdx.y;
    #pragma unroll
    for (int i = 0; i < 4; i++)
        t[y + i * 8][x] = B[(size_t)(k0 + y + i * 8) * N + n0 + x];
    __syncthreads();
    #pragma unroll
    for (int i = 0; i < 4; i++) {
        float v = t[x][y + i * 8];
        __nv_bfloat16 h, l;
        split1(v, h, l);
        size_t o = (size_t)(n0 + y + i * 8) * K + k0 + x;
        Thi[o] = h; Tlo[o] = l;
    }
}

// ---------------------------------------------------------------------------
// Elementwise / reduction kernels
// ---------------------------------------------------------------------------
__global__ void embed_kernel(const float* __restrict__ tok_emb,
                             const int* __restrict__ tokens) {
    int row = blockIdx.x;
    int s = row & (SEQ - 1);
    int d = threadIdx.x;
    int tok = tokens[row];
    int i2 = d >> 1;
    float div = expf((float)(2 * i2) * (-logf(10000.f) / (float)DIM));
    float arg = (float)s * div;
    float pe = (d & 1) ? cosf(arg) : sinf(arg);
    float v = tok_emb[(size_t)tok * DIM + d] * 16.f + pe;
    size_t o = (size_t)row * DIM + d;
    g_X[o] = v;
    __nv_bfloat16 h, l;
    split1(v, h, l);
    g_Xh[o] = h; g_Xl[o] = l;
}

__global__ void attn_kernel() {
    int n = blockIdx.x >> 3;
    int h = blockIdx.x & 7;
    __shared__ float Qs[SEQ][DH + 1];
    __shared__ float Ks[SEQ][DH + 1];
    __shared__ float Vs[SEQ][DH + 1];
    const float* base = g_QKV + (size_t)n * SEQ * 3 * DIM;
    for (int e = threadIdx.x; e < SEQ * DH; e += blockDim.x) {
        int r = e >> 5, d = e & 31;
        Qs[r][d] = base[r * 3 * DIM + h * DH + d];
        Ks[r][d] = base[r * 3 * DIM + DIM + h * DH + d];
        Vs[r][d] = base[r * 3 * DIM + 2 * DIM + h * DH + d];
    }
    __syncthreads();
    int i = threadIdx.x;
    float q[DH];
    #pragma unroll
    for (int d = 0; d < DH; d++) q[d] = Qs[i][d];
    const float scale = 0.17677669529663687f;
    float m = -1e30f, l = 0.f;
    float o[DH];
    #pragma unroll
    for (int d = 0; d < DH; d++) o[d] = 0.f;
    for (int j = 0; j < SEQ; j++) {
        float s = 0.f;
        #pragma unroll
        for (int d = 0; d < DH; d++) s += q[d] * Ks[j][d];
        s *= scale;
        if (s > m) {
            float c = expf(m - s);
            l *= c;
            #pragma unroll
            for (int d = 0; d < DH; d++) o[d] *= c;
            m = s;
        }
        float p = expf(s - m);
        l += p;
        #pragma unroll
        for (int d = 0; d < DH; d++) o[d] += p * Vs[j][d];
    }
    float inv = 1.f / l;
    size_t ob = ((size_t)n * SEQ + i) * DIM + h * DH;
    #pragma unroll
    for (int d = 0; d < DH; d += 2) {
        uint32_t hi, lo;
        split2(o[d] * inv, o[d + 1] * inv, hi, lo);
        *(uint32_t*)(g_T1h + ob + d) = hi;
        *(uint32_t*)(g_T1l + ob + d) = lo;
    }
}

__global__ void add_ln_kernel(const float* __restrict__ T,
                              const float* __restrict__ g,
                              const float* __restrict__ b) {
    int row = blockIdx.x;
    int d = threadIdx.x;
    __shared__ float sh[256];
    __shared__ float stat;
    float v = g_X[(size_t)row * DIM + d] + T[(size_t)row * DIM + d];
    sh[d] = v; __syncthreads();
    for (int s = 128; s > 0; s >>= 1) { if (d < s) sh[d] += sh[d + s]; __syncthreads(); }
    if (d == 0) stat = sh[0] * (1.f / 256.f);
    __syncthreads();
    float mean = stat;
    float diff = v - mean;
    __syncthreads();
    sh[d] = diff * diff; __syncthreads();
    for (int s = 128; s > 0; s >>= 1) { if (d < s) sh[d] += sh[d + s]; __syncthreads(); }
    if (d == 0) stat = sh[0] * (1.f / 256.f);
    __syncthreads();
    float var = stat;
    float r = diff * rsqrtf(var + 1e-5f) * g[d] + b[d];
    size_t o = (size_t)row * DIM + d;
    g_X[o] = r;
    __nv_bfloat16 h, l;
    split1(r, h, l);
    g_Xh[o] = h; g_Xl[o] = l;
}

__global__ void mean_kernel(const int* __restrict__ types,
                            const float* __restrict__ type_emb) {
    int n = blockIdx.x, d = threadIdx.x;
    float acc = 0.f;
    const float* base = g_X + (size_t)n * SEQ * DIM + d;
    for (int s = 0; s < SEQ; s++) acc += base[s * DIM];
    float v = acc * (1.f / SEQ) + type_emb[(size_t)types[n] * DIM + d];
    size_t o = (size_t)n * DIM + d;
    g_H[o] = v;
    __nv_bfloat16 h, l;
    split1(v, h, l);
    g_Hh[o] = h; g_Hl[o] = l;
}

// a_s/a_d + fused m init (self-loop max)
__global__ void asd_kernel(const float* __restrict__ asrc,
                           const float* __restrict__ adst) {
    int n = blockIdx.x;
    int w = threadIdx.x >> 5, lane = threadIdx.x & 31;
    float s1 = 0.f, s2 = 0.f;
    const float* xg = g_XG + (size_t)n * GHEADS * DIM + w * DIM;
    #pragma unroll
    for (int d = lane; d < DIM; d += 32) {
        float xv = xg[d];
        s1 += xv * asrc[w * DIM + d];
        s2 += xv * adst[w * DIM + d];
    }
    #pragma unroll
    for (int off = 16; off > 0; off >>= 1) {
        s1 += __shfl_down_sync(0xffffffffu, s1, off);
        s2 += __shfl_down_sync(0xffffffffu, s2, off);
    }
    if (lane == 0) {
        g_AS[n * GHEADS + w] = s1;
        g_AD[n * GHEADS + w] = s2;
        g_M[n * GHEADS + w] = lrelu(s1 + s2);
    }
}

__global__ void emax_kernel(const int* __restrict__ src, const int* __restrict__ dst,
                            const int* __restrict__ etype, int r) {
    int e = blockIdx.x * blockDim.x + threadIdx.x;
    if (e >= NEDGE || etype[e] != r) return;
    int s = src[e], t = dst[e];
    #pragma unroll
    for (int gh = 0; gh < GHEADS; gh++) {
        float v = lrelu(g_AS[s * GHEADS + gh] + g_AD[t * GHEADS + gh]);
        atomicMaxF(&g_M[t * GHEADS + gh], v);
    }
}

__global__ void ninit_kernel() {
    int n = blockIdx.x, d = threadIdx.x;
    #pragma unroll
    for (int gh = 0; gh < GHEADS; gh++) {
        float es = lrelu(g_AS[n * GHEADS + gh] + g_AD[n * GHEADS + gh]);
        float ws = expf(es - g_M[n * GHEADS + gh]);
        g_NUM[(size_t)n * GHEADS * DIM + gh * DIM + d] =
            ws * g_XG[(size_t)n * GHEADS * DIM + gh * DIM + d];
        if (d == 0) g_DEN[n * GHEADS + gh] = ws;
    }
}

__global__ void eacc_kernel(const int* __restrict__ src, const int* __restrict__ dst,
                            const int* __restrict__ etype, int r) {
    int e = blockIdx.x;
    if (etype[e] != r) return;
    int s = src[e], t = dst[e];
    int gh = threadIdx.x >> 6;
    int dd = threadIdx.x & 63;
    float w = expf(lrelu(g_AS[s * GHEADS + gh] + g_AD[t * GHEADS + gh])
                   - g_M[t * GHEADS + gh]);
    if (dd == 0) atomicAdd(&g_DEN[t * GHEADS + gh], w);
    const float* xs = g_XG + (size_t)s * GHEADS * DIM + gh * DIM;
    float* nm = g_NUM + (size_t)t * GHEADS * DIM + gh * DIM;
    #pragma unroll
    for (int k = 0; k < 4; k++) {
        int d = dd + 64 * k;
        atomicAdd(&nm[d], w * xs[d]);
    }
}

__global__ void comb_kernel(const float* __restrict__ gb) {
    int n = blockIdx.x, d = threadIdx.x;
    float acc = 0.f;
    #pragma unroll
    for (int gh = 0; gh < GHEADS; gh++)
        acc += g_NUM[(size_t)n * GHEADS * DIM + gh * DIM + d] / g_DEN[n * GHEADS + gh];
    g_HN[(size_t)n * DIM + d] += acc * 0.25f + gb[d];
}

__global__ void hupd_kernel() {
    size_t i = (size_t)blockIdx.x * blockDim.x + threadIdx.x;
    float v = fmaxf(g_H[i] + g_HN[i], 0.f);
    g_H[i] = v;
    __nv_bfloat16 h, l;
    split1(v, h, l);
    g_Hh[i] = h; g_Hl[i] = l;
}

__global__ void final_kernel(const float* __restrict__ log_c, float* __restrict__ out) {
    int n = blockIdx.x, d = threadIdx.x;
    __shared__ float sh[256];
    __shared__ float stat;
    float scale = sqrtf(expf(log_c[0]));
    float st = tanhf(g_TH[(size_t)n * DIM + d]) * 2.f * scale;
    sh[d] = st * st; __syncthreads();
    for (int s = 128; s > 0; s >>= 1) { if (d < s) sh[d] += sh[d + s]; __syncthreads(); }
    if (d == 0) stat = sh[0];
    __syncthreads();
    float r = fmaxf(sqrtf(stat), 1e-8f);
    if (d == 0) out[(size_t)n * 257] = coshf(r);
    out[(size_t)n * 257 + 1 + d] = sinhf(r) / r * st;
}

// ---------------------------------------------------------------------------
// Host orchestration
// ---------------------------------------------------------------------------
extern "C" void kernel_launch(void* const* d_in, const int* in_sizes, int n_in,
                              void* d_out, int out_size) {
    const float* tok_emb = (const float*)d_in[0];
    const float* Wqkv    = (const float*)d_in[1];
    const float* bqkv    = (const float*)d_in[2];
    const float* Wo      = (const float*)d_in[3];
    const float* bo      = (const float*)d_in[4];
    const float* ln1g    = (const float*)d_in[5];
    const float* ln1b    = (const float*)d_in[6];
    const float* ln2g    = (const float*)d_in[7];
    const float* ln2b    = (const float*)d_in[8];
    const float* W1      = (const float*)d_in[9];
    const float* b1      = (const float*)d_in[10];
    const float* W2      = (const float*)d_in[11];
    const float* b2      = (const float*)d_in[12];
    const float* type_emb= (const float*)d_in[13];
    const float* msg_W   = (const float*)d_in[14];
    const float* msg_b   = (const float*)d_in[15];
    const float* gat_W   = (const float*)d_in[16];
    const float* gat_b   = (const float*)d_in[17];
    const float* asrc    = (const float*)d_in[18];
    const float* adst    = (const float*)d_in[19];
    const float* spW1    = (const float*)d_in[20];
    const float* spb1    = (const float*)d_in[21];
    const float* spW2    = (const float*)d_in[22];
    const float* spb2    = (const float*)d_in[23];
    const float* log_c   = (const float*)d_in[24];
    const int*   tokens  = (const int*)d_in[25];
    const int*   types   = (const int*)d_in[26];
    const int*   eidx    = (const int*)d_in[27];
    const int*   etype   = (const int*)d_in[28];
    const int* esrc = eidx;
    const int* edst = eidx + NEDGE;
    float* out = (float*)d_out;

    float *pX, *pQKV, *pT2, *pH, *pHN, *pTH, *pXG;
    __nv_bfloat16 *pXh, *pXl, *pT1h, *pT1l, *pHh, *pHl, *pTHAh, *pTHAl,
                  *pSPHh, *pSPHl, *pWTh, *pWTl;
    cudaGetSymbolAddress((void**)&pX,    g_X);
    cudaGetSymbolAddress((void**)&pQKV,  g_QKV);
    cudaGetSymbolAddress((void**)&pT2,   g_T2);
    cudaGetSymbolAddress((void**)&pH,    g_H);
    cudaGetSymbolAddress((void**)&pHN,   g_HN);
    cudaGetSymbolAddress((void**)&pTH,   g_TH);
    cudaGetSymbolAddress((void**)&pXG,   g_XG);
    cudaGetSymbolAddress((void**)&pXh,   g_Xh);
    cudaGetSymbolAddress((void**)&pXl,   g_Xl);
    cudaGetSymbolAddress((void**)&pT1h,  g_T1h);
    cudaGetSymbolAddress((void**)&pT1l,  g_T1l);
    cudaGetSymbolAddress((void**)&pHh,   g_Hh);
    cudaGetSymbolAddress((void**)&pHl,   g_Hl);
    cudaGetSymbolAddress((void**)&pTHAh, g_THAh);
    cudaGetSymbolAddress((void**)&pTHAl, g_THAl);
    cudaGetSymbolAddress((void**)&pSPHh, g_SPHh);
    cudaGetSymbolAddress((void**)&pSPHl, g_SPHl);
    cudaGetSymbolAddress((void**)&pWTh,  g_WTh);
    cudaGetSymbolAddress((void**)&pWTl,  g_WTl);

    cudaFuncSetAttribute(gemm_bf16, cudaFuncAttributeMaxDynamicSharedMemorySize,
                         2 * STAGE_BYTES);
    const int SMEM = 2 * STAGE_BYTES;

    // 0) transpose + split all weights
    {
        dim3 blk(32, 8);
        for (int l = 0; l < 2; l++) {
            transpose_split<<<dim3(24, 8), blk>>>(Wqkv + (size_t)l * 256 * 768, pWTh + WT_QKV + l * 768 * 256, pWTl + WT_QKV + l * 768 * 256, 256, 768);
            transpose_split<<<dim3(8, 8), blk>>>(Wo + (size_t)l * 65536, pWTh + WT_WO + l * 65536, pWTl + WT_WO + l * 65536, 256, 256);
            transpose_split<<<dim3(8, 8), blk>>>(W1 + (size_t)l * 65536, pWTh + WT_W1 + l * 65536, pWTl + WT_W1 + l * 65536, 256, 256);
            transpose_split<<<dim3(8, 8), blk>>>(W2 + (size_t)l * 65536, pWTh + WT_W2 + l * 65536, pWTl + WT_W2 + l * 65536, 256, 256);
        }
        for (int r = 0; r < 3; r++)
            transpose_split<<<dim3(8, 8), blk>>>(msg_W + (size_t)r * 65536, pWTh + WT_MSG + r * 65536, pWTl + WT_MSG + r * 65536, 256, 256);
        for (int l = 0; l < 4; l++)
            transpose_split<<<dim3(32, 8), blk>>>(gat_W + (size_t)l * 256 * 1024, pWTh + WT_GAT + l * 1024 * 256, pWTl + WT_GAT + l * 1024 * 256, 256, 1024);
        transpose_split<<<dim3(16, 8), blk>>>(spW1, pWTh + WT_SP1, pWTl + WT_SP1, 256, 512);
        transpose_split<<<dim3(8, 16), blk>>>(spW2, pWTh + WT_SP2, pWTl + WT_SP2, 512, 256);
    }

    // 1) embedding + PE
    embed_kernel<<<NTOK, 256>>>(tok_emb, tokens);

    // 2) transformer encoder
    for (int l = 0; l < 2; l++) {
        gemm_bf16<<<dim3(6, NTOK / 128), 256, SMEM>>>(
            pXh, pXl, 256, pWTh + WT_QKV + l * 768 * 256, pWTl + WT_QKV + l * 768 * 256,
            bqkv + l * 768, pQKV, nullptr, nullptr, NTOK, 768, 256, 0);
        attn_kernel<<<NN * NH, 64>>>();
        gemm_bf16<<<dim3(2, NTOK / 128), 256, SMEM>>>(
            pT1h, pT1l, 256, pWTh + WT_WO + l * 65536, pWTl + WT_WO + l * 65536,
            bo + l * 256, pT2, nullptr, nullptr, NTOK, 256, 256, 0);
        add_ln_kernel<<<NTOK, 256>>>(pT2, ln1g + l * 256, ln1b + l * 256);
        gemm_bf16<<<dim3(2, NTOK / 128), 256, SMEM>>>(
            pXh, pXl, 256, pWTh + WT_W1 + l * 65536, pWTl + WT_W1 + l * 65536,
            b1 + l * 256, nullptr, pT1h, pT1l, NTOK, 256, 256, 1);
        gemm_bf16<<<dim3(2, NTOK / 128), 256, SMEM>>>(
            pT1h, pT1l, 256, pWTh + WT_W2 + l * 65536, pWTl + WT_W2 + l * 65536,
            b2 + l * 256, pT2, nullptr, nullptr, NTOK, 256, 256, 0);
        add_ln_kernel<<<NTOK, 256>>>(pT2, ln2g + l * 256, ln2b + l * 256);
    }

    // 3) mean over seq + type embedding
    mean_kernel<<<NN, 256>>>(types, type_emb);

    // 4) 4 GNN layers
    for (int l = 0; l < 4; l++) {
        cudaMemsetAsync(pHN, 0, NN * DIM * sizeof(float));
        gemm_bf16<<<dim3(6, NN / 128), 256, SMEM>>>(
            pHh, pHl, 256, pWTh + WT_MSG, pWTl + WT_MSG,
            msg_b, nullptr, pTHAh, pTHAl, NN, 768, 256, 0);
        for (int r = 0; r < 3; r++) {
            gemm_bf16<<<dim3(8, NN / 128), 256, SMEM>>>(
                pTHAh + r * 256, pTHAl + r * 256, 768,
                pWTh + WT_GAT + l * 1024 * 256, pWTl + WT_GAT + l * 1024 * 256,
                nullptr, pXG, nullptr, nullptr, NN, 1024, 256, 0);
            asd_kernel<<<NN, 128>>>(asrc + l * GHEADS * DIM, adst + l * GHEADS * DIM);
            emax_kernel<<<(NEDGE + 127) / 128, 128>>>(esrc, edst, etype, r);
            ninit_kernel<<<NN, 256>>>();
            eacc_kernel<<<NEDGE, 256>>>(esrc, edst, etype, r);
            comb_kernel<<<NN, 256>>>(gat_b + l * 256);
        }
        hupd_kernel<<<NN, 256>>>();
    }

    // 5) scoring MLP + Lorentz exp map
    gemm_bf16<<<dim3(4, NN / 128), 256, SMEM>>>(
        pHh, pHl, 256, pWTh + WT_SP1, pWTl + WT_SP1,
        spb1, nullptr, pSPHh, pSPHl, NN, 512, 256, 1);
    gemm_bf16<<<dim3(2, NN / 128), 256, SMEM>>>(
        pSPHh, pSPHl, 512, pWTh + WT_SP2, pWTl + WT_SP2,
        spb2, pTH, nullptr, nullptr, NN, 256, 512, 0);
    final_kernel<<<NN, 256>>>(log_c, out);
}

// round 5
// speedup vs baseline: 2.2041x; 1.0324x over previous
#include <cuda_runtime.h>
#include <cuda_bf16.h>
#include <math.h>
#include <stdint.h>

// ---------------------------------------------------------------------------
// Problem constants
// ---------------------------------------------------------------------------
#define NN      2048
#define SEQ     64
#define DIM     256
#define NH      8
#define DH      32
#define GHEADS  4
#define NEDGE   32768
#define NTOK    (NN*SEQ)
#define SPH     512
#define NREL    3

// ---------------------------------------------------------------------------
// Scratch (device globals)
// ---------------------------------------------------------------------------
__device__ float g_X  [NTOK*DIM];
__device__ float g_QKV[NTOK*3*DIM];
__device__ float g_T2 [NTOK*DIM];
__device__ float g_H  [NN*DIM];
__device__ float g_TH [NN*DIM];
__device__ float g_PE [SEQ*DIM];
__device__ float g_XG [NREL*NN*GHEADS*DIM];   // [r][n][gh*256+d]
__device__ float g_AS [NREL*NN*GHEADS];
__device__ float g_AD [NREL*NN*GHEADS];
__device__ float g_M  [NREL*NN*GHEADS];
__device__ float g_DEN[NREL*NN*GHEADS];
__device__ float g_NUM[NREL*NN*GHEADS*DIM];

// bf16 hi/lo split activations
__device__ __nv_bfloat16 g_Xh [NTOK*DIM],  g_Xl [NTOK*DIM];
__device__ __nv_bfloat16 g_T1h[NTOK*DIM],  g_T1l[NTOK*DIM];
__device__ __nv_bfloat16 g_Hh [NN*DIM],    g_Hl [NN*DIM];
__device__ __nv_bfloat16 g_THAh[NREL*NN*DIM], g_THAl[NREL*NN*DIM];  // relation-major
__device__ __nv_bfloat16 g_SPHh[NN*SPH],   g_SPHl[NN*SPH];

// transposed + split weights, K-major [N, K]
#define WT_QKV   0
#define WT_WO    (WT_QKV + 2*768*256)
#define WT_W1    (WT_WO  + 2*256*256)
#define WT_W2    (WT_W1  + 2*256*256)
#define WT_MSG   (WT_W2  + 2*256*256)
#define WT_GAT   (WT_MSG + 3*256*256)
#define WT_SP1   (WT_GAT + 4*1024*256)
#define WT_SP2   (WT_SP1 + 512*256)
#define WT_TOTAL (WT_SP2 + 256*512)
__device__ __nv_bfloat16 g_WTh[WT_TOTAL], g_WTl[WT_TOTAL];

// ---------------------------------------------------------------------------
// Helpers
// ---------------------------------------------------------------------------
__device__ __forceinline__ float lrelu(float x) { return x > 0.f ? x : 0.2f * x; }

__device__ __forceinline__ void atomicMaxF(float* addr, float v) {
    if (v >= 0.f) atomicMax((int*)addr, __float_as_int(v));
    else          atomicMin((unsigned int*)addr, __float_as_uint(v));
}

__device__ __forceinline__ uint32_t smem_u32(const void* p) {
    uint32_t a;
    asm("{ .reg .u64 t; cvta.to.shared.u64 t, %1; cvt.u32.u64 %0, t; }" : "=r"(a) : "l"(p));
    return a;
}

__device__ __forceinline__ void split1(float v, __nv_bfloat16& h, __nv_bfloat16& l) {
    h = __float2bfloat16_rn(v);
    l = __float2bfloat16_rn(v - __bfloat162float(h));
}

__device__ __forceinline__ void split2(float a, float b, uint32_t& hi, uint32_t& lo) {
    __nv_bfloat16 ha, la, hb, lb;
    split1(a, ha, la);
    split1(b, hb, lb);
    hi = (uint32_t)__bfloat16_as_ushort(ha) | ((uint32_t)__bfloat16_as_ushort(hb) << 16);
    lo = (uint32_t)__bfloat16_as_ushort(la) | ((uint32_t)__bfloat16_as_ushort(lb) << 16);
}

__device__ __forceinline__ void ldsm_x4(uint32_t* r, uint32_t a) {
    asm volatile("ldmatrix.sync.aligned.m8n8.x4.shared.b16 {%0,%1,%2,%3}, [%4];"
                 : "=r"(r[0]), "=r"(r[1]), "=r"(r[2]), "=r"(r[3]) : "r"(a));
}
__device__ __forceinline__ void ldsm_x2(uint32_t* r, uint32_t a) {
    asm volatile("ldmatrix.sync.aligned.m8n8.x2.shared.b16 {%0,%1}, [%2];"
                 : "=r"(r[0]), "=r"(r[1]) : "r"(a));
}

__device__ __forceinline__ void mma16816(float* c, const uint32_t* a, const uint32_t* b) {
    asm volatile(
        "mma.sync.aligned.m16n8k16.row.col.f32.bf16.bf16.f32 "
        "{%0,%1,%2,%3}, {%4,%5,%6,%7}, {%8,%9}, {%0,%1,%2,%3};"
        : "+f"(c[0]), "+f"(c[1]), "+f"(c[2]), "+f"(c[3])
        : "r"(a[0]), "r"(a[1]), "r"(a[2]), "r"(a[3]), "r"(b[0]), "r"(b[1]));
}

__device__ __forceinline__ void cp_async16(uint32_t dst, const void* src) {
    asm volatile("cp.async.cg.shared.global [%0], [%1], 16;" :: "r"(dst), "l"(src) : "memory");
}
__device__ __forceinline__ void cp_commit() {
    asm volatile("cp.async.commit_group;" ::: "memory");
}
template<int W> __device__ __forceinline__ void cp_wait() {
    asm volatile("cp.async.wait_group %0;" :: "n"(W) : "memory");
}

// ---------------------------------------------------------------------------
// Pipelined bf16-split GEMM (3-stage cp.async): C = A @ BT^T (+bias)(+relu)
// A pre-split (Ahi, Alo) [M, K] stride lda; BT pre-split (Bhi, Blo) [N, K].
// CTA tile 128x128, 8 warps, KC=32, 96KB dyn smem.
// Output: fp32 Cf and/or split (Chi, Clo). If rmaj>0, split output is written
// relation-major: index = (col>>8)*rmaj + row*256 + (col&255).
// ---------------------------------------------------------------------------
#define ARR_BYTES  8192
#define STAGE_BYTES (4*ARR_BYTES)
#define NSTAGE 3

__device__ __forceinline__ void gemm_issue(
    uint32_t sb, int stage, int tid,
    const __nv_bfloat16* Ahi, const __nv_bfloat16* Alo, int lda,
    const __nv_bfloat16* Bhi, const __nv_bfloat16* Blo, int K,
    int row0, int col0, int k0)
{
    #pragma unroll
    for (int i = 0; i < 8; i++) {
        int idx = tid + i * 256;
        int arr = idx >> 9;
        int j   = idx & 511;
        int r   = j >> 2;
        int c   = j & 3;
        uint32_t dst = sb + stage * STAGE_BYTES + arr * ARR_BYTES
                     + (uint32_t)(r * 4 + (c ^ ((r >> 1) & 3))) * 16;
        const __nv_bfloat16* src;
        if (arr == 0)      src = Ahi + (size_t)(row0 + r) * lda + k0 + c * 8;
        else if (arr == 1) src = Alo + (size_t)(row0 + r) * lda + k0 + c * 8;
        else if (arr == 2) src = Bhi + (size_t)(col0 + r) * K + k0 + c * 8;
        else               src = Blo + (size_t)(col0 + r) * K + k0 + c * 8;
        cp_async16(dst, src);
    }
    cp_commit();
}

__global__ void __launch_bounds__(256)
gemm_bf16(const __nv_bfloat16* __restrict__ Ahi, const __nv_bfloat16* __restrict__ Alo, int lda,
          const __nv_bfloat16* __restrict__ Bhi, const __nv_bfloat16* __restrict__ Blo,
          const float* __restrict__ bias,
          float* __restrict__ Cf,
          __nv_bfloat16* __restrict__ Chi, __nv_bfloat16* __restrict__ Clo,
          int M, int N, int K, int act, int rmaj) {
    extern __shared__ char sm[];
    const uint32_t sb = smem_u32(sm);
    const int tid  = threadIdx.x;
    const int lane = tid & 31;
    const int warp = tid >> 5;
    const int wm = warp & 3;
    const int wn = warp >> 2;
    const int row0 = blockIdx.y * 128;
    const int col0 = blockIdx.x * 128;

    float acc[2][8][4];
    #pragma unroll
    for (int i = 0; i < 2; i++)
        #pragma unroll
        for (int j = 0; j < 8; j++)
            #pragma unroll
            for (int k = 0; k < 4; k++) acc[i][j][k] = 0.f;

    const int nch = K >> 5;
    gemm_issue(sb, 0, tid, Ahi, Alo, lda, Bhi, Blo, K, row0, col0, 0);
    if (nch > 1)
        gemm_issue(sb, 1, tid, Ahi, Alo, lda, Bhi, Blo, K, row0, col0, 32);

    for (int ch = 0; ch < nch; ch++) {
        if (ch + 1 < nch) cp_wait<1>(); else cp_wait<0>();
        __syncthreads();

        const uint32_t base = sb + (ch % NSTAGE) * STAGE_BYTES;
        #pragma unroll
        for (int s = 0; s < 2; s++) {
            uint32_t ah[2][4], al[2][4];
            #pragma unroll
            for (int mt = 0; mt < 2; mt++) {
                int row = wm * 32 + mt * 16 + (lane & 15);
                int c = 2 * s + (lane >> 4);
                uint32_t off = (uint32_t)(row * 4 + (c ^ ((row >> 1) & 3))) * 16;
                ldsm_x4(ah[mt], base + off);
                ldsm_x4(al[mt], base + ARR_BYTES + off);
            }
            #pragma unroll
            for (int nt = 0; nt < 8; nt++) {
                int nr = wn * 64 + nt * 8 + (lane & 7);
                int c = 2 * s + ((lane >> 3) & 1);
                uint32_t off = (uint32_t)(nr * 4 + (c ^ ((nr >> 1) & 3))) * 16;
                uint32_t bh[2], bl[2];
                ldsm_x2(bh, base + 2 * ARR_BYTES + off);
                ldsm_x2(bl, base + 3 * ARR_BYTES + off);
                #pragma unroll
                for (int mt = 0; mt < 2; mt++) {
                    mma16816(acc[mt][nt], ah[mt], bh);
                    mma16816(acc[mt][nt], ah[mt], bl);
                    mma16816(acc[mt][nt], al[mt], bh);
                }
            }
        }
        __syncthreads();
        if (ch + 2 < nch)
            gemm_issue(sb, (ch + 2) % NSTAGE, tid, Ahi, Alo, lda, Bhi, Blo, K,
                       row0, col0, (ch + 2) << 5);
    }

    // epilogue
    const int g4 = lane >> 2, tig = lane & 3;
    #pragma unroll
    for (int nt = 0; nt < 8; nt++) {
        int col = col0 + wn * 64 + nt * 8 + tig * 2;
        float b0 = 0.f, b1 = 0.f;
        if (bias) { b0 = bias[col]; b1 = bias[col + 1]; }
        #pragma unroll
        for (int mt = 0; mt < 2; mt++) {
            int row = row0 + wm * 32 + mt * 16 + g4;
            float v0 = acc[mt][nt][0] + b0;
            float v1 = acc[mt][nt][1] + b1;
            float v2 = acc[mt][nt][2] + b0;
            float v3 = acc[mt][nt][3] + b1;
            if (act) {
                v0 = fmaxf(v0, 0.f); v1 = fmaxf(v1, 0.f);
                v2 = fmaxf(v2, 0.f); v3 = fmaxf(v3, 0.f);
            }
            if (Cf) {
                *(float2*)(Cf + (size_t)row * N + col)       = make_float2(v0, v1);
                *(float2*)(Cf + (size_t)(row + 8) * N + col) = make_float2(v2, v3);
            }
            if (Chi) {
                uint32_t h01, l01, h23, l23;
                split2(v0, v1, h01, l01);
                split2(v2, v3, h23, l23);
                size_t o0, o1;
                if (rmaj) {
                    o0 = (size_t)(col >> 8) * rmaj + (size_t)row * 256 + (col & 255);
                    o1 = o0 + 8 * 256;
                } else {
                    o0 = (size_t)row * N + col;
                    o1 = o0 + (size_t)8 * N;
                }
                *(uint32_t*)(Chi + o0) = h01;
                *(uint32_t*)(Clo + o0) = l01;
                *(uint32_t*)(Chi + o1) = h23;
                *(uint32_t*)(Clo + o1) = l23;
            }
        }
    }
}

// ---------------------------------------------------------------------------
// Weight transpose + split
// ---------------------------------------------------------------------------
__global__ void transpose_split(const float* __restrict__ B,
                                __nv_bfloat16* __restrict__ Thi,
                                __nv_bfloat16* __restrict__ Tlo,
                                int K, int N) {
    __shared__ float t[32][33];
    int n0 = blockIdx.x * 32, k0 = blockIdx.y * 32;
    int x = threadIdx.x, y = threadIdx.y;
    #pragma unroll
    for (int i = 0; i < 4; i++)
        t[y + i * 8][x] = B[(size_t)(k0 + y + i * 8) * N + n0 + x];
    __syncthreads();
    #pragma unroll
    for (int i = 0; i < 4; i++) {
        float v = t[x][y + i * 8];
        __nv_bfloat16 h, l;
        split1(v, h, l);
        size_t o = (size_t)(n0 + y + i * 8) * K + k0 + x;
        Thi[o] = h; Tlo[o] = l;
    }
}

// ---------------------------------------------------------------------------
// PE table + embedding
// ---------------------------------------------------------------------------
__global__ void pe_kernel() {
    int s = blockIdx.x, d = threadIdx.x;
    int i2 = d >> 1;
    float div = expf((float)(2 * i2) * (-logf(10000.f) / (float)DIM));
    float arg = (float)s * div;
    g_PE[s * DIM + d] = (d & 1) ? cosf(arg) : sinf(arg);
}

__global__ void embed_kernel(const float* __restrict__ tok_emb,
                             const int* __restrict__ tokens) {
    int row = blockIdx.x;
    int s = row & (SEQ - 1);
    int d = threadIdx.x;
    int tok = tokens[row];
    float v = tok_emb[(size_t)tok * DIM + d] * 16.f + g_PE[s * DIM + d];
    size_t o = (size_t)row * DIM + d;
    g_X[o] = v;
    __nv_bfloat16 h, l;
    split1(v, h, l);
    g_Xh[o] = h; g_Xl[o] = l;
}

// ---------------------------------------------------------------------------
// Attention
// ---------------------------------------------------------------------------
__global__ void attn_kernel() {
    int n = blockIdx.x >> 3;
    int h = blockIdx.x & 7;
    __shared__ float Qs[SEQ][DH + 1];
    __shared__ float Ks[SEQ][DH + 1];
    __shared__ float Vs[SEQ][DH + 1];
    const float* base = g_QKV + (size_t)n * SEQ * 3 * DIM;
    for (int e = threadIdx.x; e < SEQ * DH; e += blockDim.x) {
        int r = e >> 5, d = e & 31;
        Qs[r][d] = base[r * 3 * DIM + h * DH + d];
        Ks[r][d] = base[r * 3 * DIM + DIM + h * DH + d];
        Vs[r][d] = base[r * 3 * DIM + 2 * DIM + h * DH + d];
    }
    __syncthreads();
    int i = threadIdx.x;
    float q[DH];
    #pragma unroll
    for (int d = 0; d < DH; d++) q[d] = Qs[i][d];
    const float scale = 0.17677669529663687f;
    float m = -1e30f, l = 0.f;
    float o[DH];
    #pragma unroll
    for (int d = 0; d < DH; d++) o[d] = 0.f;
    for (int j = 0; j < SEQ; j++) {
        float s0 = 0.f, s1 = 0.f, s2 = 0.f, s3 = 0.f;
        #pragma unroll
        for (int d = 0; d < DH; d += 4) {
            s0 += q[d]     * Ks[j][d];
            s1 += q[d + 1] * Ks[j][d + 1];
            s2 += q[d + 2] * Ks[j][d + 2];
            s3 += q[d + 3] * Ks[j][d + 3];
        }
        float s = ((s0 + s1) + (s2 + s3)) * scale;
        if (s > m) {
            float c = expf(m - s);
            l *= c;
            #pragma unroll
            for (int d = 0; d < DH; d++) o[d] *= c;
            m = s;
        }
        float p = expf(s - m);
        l += p;
        #pragma unroll
        for (int d = 0; d < DH; d++) o[d] += p * Vs[j][d];
    }
    float inv = 1.f / l;
    size_t ob = ((size_t)n * SEQ + i) * DIM + h * DH;
    #pragma unroll
    for (int d = 0; d < DH; d += 2) {
        uint32_t hi, lo;
        split2(o[d] * inv, o[d + 1] * inv, hi, lo);
        *(uint32_t*)(g_T1h + ob + d) = hi;
        *(uint32_t*)(g_T1l + ob + d) = lo;
    }
}

// ---------------------------------------------------------------------------
// LayerNorm(X + T) -> X (+ split)
// ---------------------------------------------------------------------------
__global__ void add_ln_kernel(const float* __restrict__ T,
                              const float* __restrict__ g,
                              const float* __restrict__ b) {
    int row = blockIdx.x;
    int d = threadIdx.x;
    __shared__ float sh[256];
    __shared__ float stat;
    float v = g_X[(size_t)row * DIM + d] + T[(size_t)row * DIM + d];
    sh[d] = v; __syncthreads();
    for (int s = 128; s > 0; s >>= 1) { if (d < s) sh[d] += sh[d + s]; __syncthreads(); }
    if (d == 0) stat = sh[0] * (1.f / 256.f);
    __syncthreads();
    float mean = stat;
    float diff = v - mean;
    __syncthreads();
    sh[d] = diff * diff; __syncthreads();
    for (int s = 128; s > 0; s >>= 1) { if (d < s) sh[d] += sh[d + s]; __syncthreads(); }
    if (d == 0) stat = sh[0] * (1.f / 256.f);
    __syncthreads();
    float var = stat;
    float r = diff * rsqrtf(var + 1e-5f) * g[d] + b[d];
    size_t o = (size_t)row * DIM + d;
    g_X[o] = r;
    __nv_bfloat16 h, l;
    split1(r, h, l);
    g_Xh[o] = h; g_Xl[o] = l;
}

__global__ void mean_kernel(const int* __restrict__ types,
                            const float* __restrict__ type_emb) {
    int n = blockIdx.x, d = threadIdx.x;
    float acc = 0.f;
    const float* base = g_X + (size_t)n * SEQ * DIM + d;
    for (int s = 0; s < SEQ; s++) acc += base[s * DIM];
    float v = acc * (1.f / SEQ) + type_emb[(size_t)types[n] * DIM + d];
    size_t o = (size_t)n * DIM + d;
    g_H[o] = v;
    __nv_bfloat16 h, l;
    split1(v, h, l);
    g_Hh[o] = h; g_Hl[o] = l;
}

// ---------------------------------------------------------------------------
// GNN kernels — batched across relations
// ---------------------------------------------------------------------------
// a_s/a_d + fused self-loop max. grid NREL*NN, block 128 (warp per head).
__global__ void asd_kernel(const float* __restrict__ asrc,
                           const float* __restrict__ adst) {
    int i = blockIdx.x;                 // r*NN + n
    int w = threadIdx.x >> 5, lane = threadIdx.x & 31;
    float s1 = 0.f, s2 = 0.f;
    const float* xg = g_XG + (size_t)i * GHEADS * DIM + w * DIM;
    #pragma unroll
    for (int d = lane; d < DIM; d += 32) {
        float xv = xg[d];
        s1 += xv * asrc[w * DIM + d];
        s2 += xv * adst[w * DIM + d];
    }
    #pragma unroll
    for (int off = 16; off > 0; off >>= 1) {
        s1 += __shfl_down_sync(0xffffffffu, s1, off);
        s2 += __shfl_down_sync(0xffffffffu, s2, off);
    }
    if (lane == 0) {
        g_AS[i * GHEADS + w] = s1;
        g_AD[i * GHEADS + w] = s2;
        g_M[i * GHEADS + w] = lrelu(s1 + s2);
    }
}

// segment max, all edges in one launch. thread per edge.
__global__ void emax_kernel(const int* __restrict__ src, const int* __restrict__ dst,
                            const int* __restrict__ etype) {
    int e = blockIdx.x * blockDim.x + threadIdx.x;
    if (e >= NEDGE) return;
    int r = etype[e];
    int s = r * NN + src[e], t = r * NN + dst[e];
    #pragma unroll
    for (int gh = 0; gh < GHEADS; gh++) {
        float v = lrelu(g_AS[s * GHEADS + gh] + g_AD[t * GHEADS + gh]);
        atomicMaxF(&g_M[t * GHEADS + gh], v);
    }
}

// init NUM/DEN with self-loop. grid NREL*NN, block 256.
__global__ void ninit_kernel() {
    int i = blockIdx.x, d = threadIdx.x;
    #pragma unroll
    for (int gh = 0; gh < GHEADS; gh++) {
        float es = lrelu(g_AS[i * GHEADS + gh] + g_AD[i * GHEADS + gh]);
        float ws = expf(es - g_M[i * GHEADS + gh]);
        g_NUM[(size_t)i * GHEADS * DIM + gh * DIM + d] =
            ws * g_XG[(size_t)i * GHEADS * DIM + gh * DIM + d];
        if (d == 0) g_DEN[i * GHEADS + gh] = ws;
    }
}

// edge accumulation, all edges. block (256 thr) per edge.
__global__ void eacc_kernel(const int* __restrict__ src, const int* __restrict__ dst,
                            const int* __restrict__ etype) {
    int e = blockIdx.x;
    int r = etype[e];
    int s = r * NN + src[e], t = r * NN + dst[e];
    int gh = threadIdx.x >> 6;
    int dd = threadIdx.x & 63;
    float w = expf(lrelu(g_AS[s * GHEADS + gh] + g_AD[t * GHEADS + gh])
                   - g_M[t * GHEADS + gh]);
    if (dd == 0) atomicAdd(&g_DEN[t * GHEADS + gh], w);
    const float* xs = g_XG + (size_t)s * GHEADS * DIM + gh * DIM;
    float* nm = g_NUM + (size_t)t * GHEADS * DIM + gh * DIM;
    #pragma unroll
    for (int k = 0; k < 4; k++) {
        int d = dd + 64 * k;
        atomicAdd(&nm[d], w * xs[d]);
    }
}

// h = relu(h + sum_r mean_gh(num/den) + 3*gb). grid NN, block 256. +split
__global__ void combupd_kernel(const float* __restrict__ gb) {
    int n = blockIdx.x, d = threadIdx.x;
    float acc = 0.f;
    #pragma unroll
    for (int r = 0; r < NREL; r++) {
        int i = r * NN + n;
        #pragma unroll
        for (int gh = 0; gh < GHEADS; gh++)
            acc += g_NUM[(size_t)i * GHEADS * DIM + gh * DIM + d] / g_DEN[i * GHEADS + gh];
    }
    size_t o = (size_t)n * DIM + d;
    float v = fmaxf(g_H[o] + acc * 0.25f + 3.f * gb[d], 0.f);
    g_H[o] = v;
    __nv_bfloat16 h, l;
    split1(v, h, l);
    g_Hh[o] = h; g_Hl[o] = l;
}

__global__ void final_kernel(const float* __restrict__ log_c, float* __restrict__ out) {
    int n = blockIdx.x, d = threadIdx.x;
    __shared__ float sh[256];
    __shared__ float stat;
    float scale = sqrtf(expf(log_c[0]));
    float st = tanhf(g_TH[(size_t)n * DIM + d]) * 2.f * scale;
    sh[d] = st * st; __syncthreads();
    for (int s = 128; s > 0; s >>= 1) { if (d < s) sh[d] += sh[d + s]; __syncthreads(); }
    if (d == 0) stat = sh[0];
    __syncthreads();
    float r = fmaxf(sqrtf(stat), 1e-8f);
    if (d == 0) out[(size_t)n * 257] = coshf(r);
    out[(size_t)n * 257 + 1 + d] = sinhf(r) / r * st;
}

// ---------------------------------------------------------------------------
// Host orchestration
// ---------------------------------------------------------------------------
extern "C" void kernel_launch(void* const* d_in, const int* in_sizes, int n_in,
                              void* d_out, int out_size) {
    const float* tok_emb = (const float*)d_in[0];
    const float* Wqkv    = (const float*)d_in[1];
    const float* bqkv    = (const float*)d_in[2];
    const float* Wo      = (const float*)d_in[3];
    const float* bo      = (const float*)d_in[4];
    const float* ln1g    = (const float*)d_in[5];
    const float* ln1b    = (const float*)d_in[6];
    const float* ln2g    = (const float*)d_in[7];
    const float* ln2b    = (const float*)d_in[8];
    const float* W1      = (const float*)d_in[9];
    const float* b1      = (const float*)d_in[10];
    const float* W2      = (const float*)d_in[11];
    const float* b2      = (const float*)d_in[12];
    const float* type_emb= (const float*)d_in[13];
    const float* msg_W   = (const float*)d_in[14];
    const float* msg_b   = (const float*)d_in[15];
    const float* gat_W   = (const float*)d_in[16];
    const float* gat_b   = (const float*)d_in[17];
    const float* asrc    = (const float*)d_in[18];
    const float* adst    = (const float*)d_in[19];
    const float* spW1    = (const float*)d_in[20];
    const float* spb1    = (const float*)d_in[21];
    const float* spW2    = (const float*)d_in[22];
    const float* spb2    = (const float*)d_in[23];
    const float* log_c   = (const float*)d_in[24];
    const int*   tokens  = (const int*)d_in[25];
    const int*   types   = (const int*)d_in[26];
    const int*   eidx    = (const int*)d_in[27];
    const int*   etype   = (const int*)d_in[28];
    const int* esrc = eidx;
    const int* edst = eidx + NEDGE;
    float* out = (float*)d_out;

    float *pQKV, *pT2, *pH, *pTH, *pXG;
    __nv_bfloat16 *pXh, *pXl, *pT1h, *pT1l, *pHh, *pHl, *pTHAh, *pTHAl,
                  *pSPHh, *pSPHl, *pWTh, *pWTl;
    cudaGetSymbolAddress((void**)&pQKV,  g_QKV);
    cudaGetSymbolAddress((void**)&pT2,   g_T2);
    cudaGetSymbolAddress((void**)&pH,    g_H);
    cudaGetSymbolAddress((void**)&pTH,   g_TH);
    cudaGetSymbolAddress((void**)&pXG,   g_XG);
    cudaGetSymbolAddress((void**)&pXh,   g_Xh);
    cudaGetSymbolAddress((void**)&pXl,   g_Xl);
    cudaGetSymbolAddress((void**)&pT1h,  g_T1h);
    cudaGetSymbolAddress((void**)&pT1l,  g_T1l);
    cudaGetSymbolAddress((void**)&pHh,   g_Hh);
    cudaGetSymbolAddress((void**)&pHl,   g_Hl);
    cudaGetSymbolAddress((void**)&pTHAh, g_THAh);
    cudaGetSymbolAddress((void**)&pTHAl, g_THAl);
    cudaGetSymbolAddress((void**)&pSPHh, g_SPHh);
    cudaGetSymbolAddress((void**)&pSPHl, g_SPHl);
    cudaGetSymbolAddress((void**)&pWTh,  g_WTh);
    cudaGetSymbolAddress((void**)&pWTl,  g_WTl);

    cudaFuncSetAttribute(gemm_bf16, cudaFuncAttributeMaxDynamicSharedMemorySize,
                         NSTAGE * STAGE_BYTES);
    const int SMEM = NSTAGE * STAGE_BYTES;

    // 0) transpose + split all weights; PE table
    {
        dim3 blk(32, 8);
        for (int l = 0; l < 2; l++) {
            transpose_split<<<dim3(24, 8), blk>>>(Wqkv + (size_t)l * 256 * 768, pWTh + WT_QKV + l * 768 * 256, pWTl + WT_QKV + l * 768 * 256, 256, 768);
            transpose_split<<<dim3(8, 8), blk>>>(Wo + (size_t)l * 65536, pWTh + WT_WO + l * 65536, pWTl + WT_WO + l * 65536, 256, 256);
            transpose_split<<<dim3(8, 8), blk>>>(W1 + (size_t)l * 65536, pWTh + WT_W1 + l * 65536, pWTl + WT_W1 + l * 65536, 256, 256);
            transpose_split<<<dim3(8, 8), blk>>>(W2 + (size_t)l * 65536, pWTh + WT_W2 + l * 65536, pWTl + WT_W2 + l * 65536, 256, 256);
        }
        for (int r = 0; r < 3; r++)
            transpose_split<<<dim3(8, 8), blk>>>(msg_W + (size_t)r * 65536, pWTh + WT_MSG + r * 65536, pWTl + WT_MSG + r * 65536, 256, 256);
        for (int l = 0; l < 4; l++)
            transpose_split<<<dim3(32, 8), blk>>>(gat_W + (size_t)l * 256 * 1024, pWTh + WT_GAT + l * 1024 * 256, pWTl + WT_GAT + l * 1024 * 256, 256, 1024);
        transpose_split<<<dim3(16, 8), blk>>>(spW1, pWTh + WT_SP1, pWTl + WT_SP1, 256, 512);
        transpose_split<<<dim3(8, 16), blk>>>(spW2, pWTh + WT_SP2, pWTl + WT_SP2, 512, 256);
        pe_kernel<<<SEQ, 256>>>();
    }

    // 1) embedding + PE
    embed_kernel<<<NTOK, 256>>>(tok_emb, tokens);

    // 2) transformer encoder
    for (int l = 0; l < 2; l++) {
        gemm_bf16<<<dim3(6, NTOK / 128), 256, SMEM>>>(
            pXh, pXl, 256, pWTh + WT_QKV + l * 768 * 256, pWTl + WT_QKV + l * 768 * 256,
            bqkv + l * 768, pQKV, nullptr, nullptr, NTOK, 768, 256, 0, 0);
        attn_kernel<<<NN * NH, 64>>>();
        gemm_bf16<<<dim3(2, NTOK / 128), 256, SMEM>>>(
            pT1h, pT1l, 256, pWTh + WT_WO + l * 65536, pWTl + WT_WO + l * 65536,
            bo + l * 256, pT2, nullptr, nullptr, NTOK, 256, 256, 0, 0);
        add_ln_kernel<<<NTOK, 256>>>(pT2, ln1g + l * 256, ln1b + l * 256);
        gemm_bf16<<<dim3(2, NTOK / 128), 256, SMEM>>>(
            pXh, pXl, 256, pWTh + WT_W1 + l * 65536, pWTl + WT_W1 + l * 65536,
            b1 + l * 256, nullptr, pT1h, pT1l, NTOK, 256, 256, 1, 0);
        gemm_bf16<<<dim3(2, NTOK / 128), 256, SMEM>>>(
            pT1h, pT1l, 256, pWTh + WT_W2 + l * 65536, pWTl + WT_W2 + l * 65536,
            b2 + l * 256, pT2, nullptr, nullptr, NTOK, 256, 256, 0, 0);
        add_ln_kernel<<<NTOK, 256>>>(pT2, ln2g + l * 256, ln2b + l * 256);
    }

    // 3) mean over seq + type embedding
    mean_kernel<<<NN, 256>>>(types, type_emb);

    // 4) 4 GNN layers (relations batched)
    for (int l = 0; l < 4; l++) {
        // msg: [2048,768] -> relation-major split [3][2048][256]
        gemm_bf16<<<dim3(6, NN / 128), 256, SMEM>>>(
            pHh, pHl, 256, pWTh + WT_MSG, pWTl + WT_MSG,
            msg_b, nullptr, pTHAh, pTHAl, NN, 768, 256, 0, NN * DIM);
        // gat: single GEMM over all 3 relations, M = 3*2048
        gemm_bf16<<<dim3(8, NREL * NN / 128), 256, SMEM>>>(
            pTHAh, pTHAl, 256,
            pWTh + WT_GAT + l * 1024 * 256, pWTl + WT_GAT + l * 1024 * 256,
            nullptr, pXG, nullptr, nullptr, NREL * NN, 1024, 256, 0, 0);
        asd_kernel<<<NREL * NN, 128>>>(asrc + l * GHEADS * DIM, adst + l * GHEADS * DIM);
        emax_kernel<<<NEDGE / 128, 128>>>(esrc, edst, etype);
        ninit_kernel<<<NREL * NN, 256>>>();
        eacc_kernel<<<NEDGE, 256>>>(esrc, edst, etype);
        combupd_kernel<<<NN, 256>>>(gat_b + l * 256);
    }

    // 5) scoring MLP + Lorentz exp map
    gemm_bf16<<<dim3(4, NN / 128), 256, SMEM>>>(
        pHh, pHl, 256, pWTh + WT_SP1, pWTl + WT_SP1,
        spb1, nullptr, pSPHh, pSPHl, NN, 512, 256, 1, 0);
    gemm_bf16<<<dim3(2, NN / 128), 256, SMEM>>>(
        pSPHh, pSPHl, 512, pWTh + WT_SP2, pWTl + WT_SP2,
        spb2, pTH, nullptr, nullptr, NN, 256, 512, 0, 0);
    final_kernel<<<NN, 256>>>(log_c, out);
}

// round 6
// speedup vs baseline: 2.5993x; 1.1793x over previous
#include <cuda_runtime.h>
#include <cuda_bf16.h>
#include <math.h>
#include <stdint.h>

// ---------------------------------------------------------------------------
// Problem constants
// ---------------------------------------------------------------------------
#define NN      2048
#define SEQ     64
#define DIM     256
#define NH      8
#define DH      32
#define GHEADS  4
#define NEDGE   32768
#define NTOK    (NN*SEQ)
#define SPH     512
#define NREL    3

// ---------------------------------------------------------------------------
// Scratch (device globals)
// ---------------------------------------------------------------------------
__device__ float g_QKV[NTOK*3*DIM];
__device__ float g_H  [NN*DIM];
__device__ float g_TH [NN*DIM];
__device__ float g_PE [SEQ*DIM];
__device__ float g_XG [NREL*NN*GHEADS*DIM];
__device__ float g_AS [NREL*NN*GHEADS];
__device__ float g_AD [NREL*NN*GHEADS];
__device__ float g_M  [NREL*NN*GHEADS];
__device__ float g_DEN[NREL*NN*GHEADS];
__device__ float g_NUM[NREL*NN*GHEADS*DIM];

// bf16 hi/lo split activations (the only storage for X)
__device__ __nv_bfloat16 g_Xh [NTOK*DIM],  g_Xl [NTOK*DIM];
__device__ __nv_bfloat16 g_T1h[NTOK*DIM],  g_T1l[NTOK*DIM];
__device__ __nv_bfloat16 g_Hh [NN*DIM],    g_Hl [NN*DIM];
__device__ __nv_bfloat16 g_THAh[NREL*NN*DIM], g_THAl[NREL*NN*DIM];
__device__ __nv_bfloat16 g_SPHh[NN*SPH],   g_SPHl[NN*SPH];

// transposed + split weights, K-major [N, K]
#define WT_QKV   0
#define WT_WO    (WT_QKV + 2*768*256)
#define WT_W1    (WT_WO  + 2*256*256)
#define WT_W2    (WT_W1  + 2*256*256)
#define WT_MSG   (WT_W2  + 2*256*256)
#define WT_GAT   (WT_MSG + 3*256*256)
#define WT_SP1   (WT_GAT + 4*1024*256)
#define WT_SP2   (WT_SP1 + 512*256)
#define WT_TOTAL (WT_SP2 + 256*512)
__device__ __nv_bfloat16 g_WTh[WT_TOTAL], g_WTl[WT_TOTAL];

// ---------------------------------------------------------------------------
// Helpers
// ---------------------------------------------------------------------------
__device__ __forceinline__ float lrelu(float x) { return x > 0.f ? x : 0.2f * x; }

__device__ __forceinline__ void atomicMaxF(float* addr, float v) {
    if (v >= 0.f) atomicMax((int*)addr, __float_as_int(v));
    else          atomicMin((unsigned int*)addr, __float_as_uint(v));
}

__device__ __forceinline__ uint32_t smem_u32(const void* p) {
    uint32_t a;
    asm("{ .reg .u64 t; cvta.to.shared.u64 t, %1; cvt.u32.u64 %0, t; }" : "=r"(a) : "l"(p));
    return a;
}

__device__ __forceinline__ void split1(float v, __nv_bfloat16& h, __nv_bfloat16& l) {
    h = __float2bfloat16_rn(v);
    l = __float2bfloat16_rn(v - __bfloat162float(h));
}

__device__ __forceinline__ void split2(float a, float b, uint32_t& hi, uint32_t& lo) {
    __nv_bfloat16 ha, la, hb, lb;
    split1(a, ha, la);
    split1(b, hb, lb);
    hi = (uint32_t)__bfloat16_as_ushort(ha) | ((uint32_t)__bfloat16_as_ushort(hb) << 16);
    lo = (uint32_t)__bfloat16_as_ushort(la) | ((uint32_t)__bfloat16_as_ushort(lb) << 16);
}

__device__ __forceinline__ float bflo(uint32_t x) {
    return __bfloat162float(__ushort_as_bfloat16((unsigned short)(x & 0xffffu)));
}
__device__ __forceinline__ float bfhi(uint32_t x) {
    return __bfloat162float(__ushort_as_bfloat16((unsigned short)(x >> 16)));
}

__device__ __forceinline__ void ldsm_x4(uint32_t* r, uint32_t a) {
    asm volatile("ldmatrix.sync.aligned.m8n8.x4.shared.b16 {%0,%1,%2,%3}, [%4];"
                 : "=r"(r[0]), "=r"(r[1]), "=r"(r[2]), "=r"(r[3]) : "r"(a));
}
__device__ __forceinline__ void ldsm_x2(uint32_t* r, uint32_t a) {
    asm volatile("ldmatrix.sync.aligned.m8n8.x2.shared.b16 {%0,%1}, [%2];"
                 : "=r"(r[0]), "=r"(r[1]) : "r"(a));
}

__device__ __forceinline__ void mma16816(float* c, const uint32_t* a, const uint32_t* b) {
    asm volatile(
        "mma.sync.aligned.m16n8k16.row.col.f32.bf16.bf16.f32 "
        "{%0,%1,%2,%3}, {%4,%5,%6,%7}, {%8,%9}, {%0,%1,%2,%3};"
        : "+f"(c[0]), "+f"(c[1]), "+f"(c[2]), "+f"(c[3])
        : "r"(a[0]), "r"(a[1]), "r"(a[2]), "r"(a[3]), "r"(b[0]), "r"(b[1]));
}

__device__ __forceinline__ void cp_async16(uint32_t dst, const void* src) {
    asm volatile("cp.async.cg.shared.global [%0], [%1], 16;" :: "r"(dst), "l"(src) : "memory");
}
__device__ __forceinline__ void cp_commit() {
    asm volatile("cp.async.commit_group;" ::: "memory");
}
template<int W> __device__ __forceinline__ void cp_wait() {
    asm volatile("cp.async.wait_group %0;" :: "n"(W) : "memory");
}

// ---------------------------------------------------------------------------
// Generic pipelined bf16-split GEMM (unchanged from round 5)
// ---------------------------------------------------------------------------
#define ARR_BYTES  8192
#define STAGE_BYTES (4*ARR_BYTES)
#define NSTAGE 3

__device__ __forceinline__ void gemm_issue(
    uint32_t sb, int stage, int tid,
    const __nv_bfloat16* Ahi, const __nv_bfloat16* Alo, int lda,
    const __nv_bfloat16* Bhi, const __nv_bfloat16* Blo, int K,
    int row0, int col0, int k0)
{
    #pragma unroll
    for (int i = 0; i < 8; i++) {
        int idx = tid + i * 256;
        int arr = idx >> 9;
        int j   = idx & 511;
        int r   = j >> 2;
        int c   = j & 3;
        uint32_t dst = sb + stage * STAGE_BYTES + arr * ARR_BYTES
                     + (uint32_t)(r * 4 + (c ^ ((r >> 1) & 3))) * 16;
        const __nv_bfloat16* src;
        if (arr == 0)      src = Ahi + (size_t)(row0 + r) * lda + k0 + c * 8;
        else if (arr == 1) src = Alo + (size_t)(row0 + r) * lda + k0 + c * 8;
        else if (arr == 2) src = Bhi + (size_t)(col0 + r) * K + k0 + c * 8;
        else               src = Blo + (size_t)(col0 + r) * K + k0 + c * 8;
        cp_async16(dst, src);
    }
    cp_commit();
}

__global__ void __launch_bounds__(256)
gemm_bf16(const __nv_bfloat16* __restrict__ Ahi, const __nv_bfloat16* __restrict__ Alo, int lda,
          const __nv_bfloat16* __restrict__ Bhi, const __nv_bfloat16* __restrict__ Blo,
          const float* __restrict__ bias,
          float* __restrict__ Cf,
          __nv_bfloat16* __restrict__ Chi, __nv_bfloat16* __restrict__ Clo,
          int M, int N, int K, int act, int rmaj) {
    extern __shared__ char sm[];
    const uint32_t sb = smem_u32(sm);
    const int tid  = threadIdx.x;
    const int lane = tid & 31;
    const int warp = tid >> 5;
    const int wm = warp & 3;
    const int wn = warp >> 2;
    const int row0 = blockIdx.y * 128;
    const int col0 = blockIdx.x * 128;

    float acc[2][8][4];
    #pragma unroll
    for (int i = 0; i < 2; i++)
        #pragma unroll
        for (int j = 0; j < 8; j++)
            #pragma unroll
            for (int k = 0; k < 4; k++) acc[i][j][k] = 0.f;

    const int nch = K >> 5;
    gemm_issue(sb, 0, tid, Ahi, Alo, lda, Bhi, Blo, K, row0, col0, 0);
    if (nch > 1)
        gemm_issue(sb, 1, tid, Ahi, Alo, lda, Bhi, Blo, K, row0, col0, 32);

    for (int ch = 0; ch < nch; ch++) {
        if (ch + 1 < nch) cp_wait<1>(); else cp_wait<0>();
        __syncthreads();

        const uint32_t base = sb + (ch % NSTAGE) * STAGE_BYTES;
        #pragma unroll
        for (int s = 0; s < 2; s++) {
            uint32_t ah[2][4], al[2][4];
            #pragma unroll
            for (int mt = 0; mt < 2; mt++) {
                int row = wm * 32 + mt * 16 + (lane & 15);
                int c = 2 * s + (lane >> 4);
                uint32_t off = (uint32_t)(row * 4 + (c ^ ((row >> 1) & 3))) * 16;
                ldsm_x4(ah[mt], base + off);
                ldsm_x4(al[mt], base + ARR_BYTES + off);
            }
            #pragma unroll
            for (int nt = 0; nt < 8; nt++) {
                int nr = wn * 64 + nt * 8 + (lane & 7);
                int c = 2 * s + ((lane >> 3) & 1);
                uint32_t off = (uint32_t)(nr * 4 + (c ^ ((nr >> 1) & 3))) * 16;
                uint32_t bh[2], bl[2];
                ldsm_x2(bh, base + 2 * ARR_BYTES + off);
                ldsm_x2(bl, base + 3 * ARR_BYTES + off);
                #pragma unroll
                for (int mt = 0; mt < 2; mt++) {
                    mma16816(acc[mt][nt], ah[mt], bh);
                    mma16816(acc[mt][nt], ah[mt], bl);
                    mma16816(acc[mt][nt], al[mt], bh);
                }
            }
        }
        __syncthreads();
        if (ch + 2 < nch)
            gemm_issue(sb, (ch + 2) % NSTAGE, tid, Ahi, Alo, lda, Bhi, Blo, K,
                       row0, col0, (ch + 2) << 5);
    }

    const int g4 = lane >> 2, tig = lane & 3;
    #pragma unroll
    for (int nt = 0; nt < 8; nt++) {
        int col = col0 + wn * 64 + nt * 8 + tig * 2;
        float b0 = 0.f, b1 = 0.f;
        if (bias) { b0 = bias[col]; b1 = bias[col + 1]; }
        #pragma unroll
        for (int mt = 0; mt < 2; mt++) {
            int row = row0 + wm * 32 + mt * 16 + g4;
            float v0 = acc[mt][nt][0] + b0;
            float v1 = acc[mt][nt][1] + b1;
            float v2 = acc[mt][nt][2] + b0;
            float v3 = acc[mt][nt][3] + b1;
            if (act) {
                v0 = fmaxf(v0, 0.f); v1 = fmaxf(v1, 0.f);
                v2 = fmaxf(v2, 0.f); v3 = fmaxf(v3, 0.f);
            }
            if (Cf) {
                *(float2*)(Cf + (size_t)row * N + col)       = make_float2(v0, v1);
                *(float2*)(Cf + (size_t)(row + 8) * N + col) = make_float2(v2, v3);
            }
            if (Chi) {
                uint32_t h01, l01, h23, l23;
                split2(v0, v1, h01, l01);
                split2(v2, v3, h23, l23);
                size_t o0, o1;
                if (rmaj) {
                    o0 = (size_t)(col >> 8) * rmaj + (size_t)row * 256 + (col & 255);
                    o1 = o0 + 8 * 256;
                } else {
                    o0 = (size_t)row * N + col;
                    o1 = o0 + (size_t)8 * N;
                }
                *(uint32_t*)(Chi + o0) = h01;
                *(uint32_t*)(Clo + o0) = l01;
                *(uint32_t*)(Chi + o1) = h23;
                *(uint32_t*)(Clo + o1) = l23;
            }
        }
    }
}

// ---------------------------------------------------------------------------
// Fused GEMM + residual + LayerNorm: X = LN(X + A@BT^T + bias) (splits in/out)
// Fixed N=256, K=256. CTA tile 128x256, 512 threads (16 warps, 4x4).
// 3-stage cp.async (48KB/stage). In-place on (Xh, Xl).
// ---------------------------------------------------------------------------
#define LSTG 49152   // Ahi 8K + Alo 8K + Bhi 16K + Blo 16K

__device__ __forceinline__ void gemm_ln_issue(
    uint32_t sb, int stage, int tid, int row0, int k0,
    const __nv_bfloat16* Ahi, const __nv_bfloat16* Alo,
    const __nv_bfloat16* Bhi, const __nv_bfloat16* Blo)
{
    #pragma unroll
    for (int i = 0; i < 6; i++) {
        int idx = tid + i * 512;      // 0..3071
        uint32_t stg = sb + stage * LSTG;
        const __nv_bfloat16* src;
        uint32_t dst;
        if (idx < 1024) {             // A tiles, 128 rows
            int j = idx & 511;
            int r = j >> 2, c = j & 3;
            dst = stg + ((idx >> 9) ? 8192u : 0u)
                + (uint32_t)(r * 4 + (c ^ ((r >> 1) & 3))) * 16;
            src = ((idx >> 9) ? Alo : Ahi) + (size_t)(row0 + r) * 256 + k0 + c * 8;
        } else {                      // B tiles, 256 rows
            int j = (idx - 1024) & 1023;
            int r = j >> 2, c = j & 3;
            dst = stg + ((idx >= 2048) ? 32768u : 16384u)
                + (uint32_t)(r * 4 + (c ^ ((r >> 1) & 3))) * 16;
            src = ((idx >= 2048) ? Blo : Bhi) + (size_t)r * 256 + k0 + c * 8;
        }
        cp_async16(dst, src);
    }
    cp_commit();
}

__global__ void __launch_bounds__(512)
gemm_ln(const __nv_bfloat16* __restrict__ Ahi, const __nv_bfloat16* __restrict__ Alo,
        const __nv_bfloat16* __restrict__ Bhi, const __nv_bfloat16* __restrict__ Blo,
        const float* __restrict__ bias,
        const float* __restrict__ lng, const float* __restrict__ lnb,
        __nv_bfloat16* Xh, __nv_bfloat16* Xl) {
    extern __shared__ char sm[];
    const uint32_t sb = smem_u32(sm);
    float* s_sum  = (float*)(sm + 3 * LSTG);          // [128][4][2]
    float* s_g    = (float*)(sm + 3 * LSTG + 4096);
    float* s_b    = s_g + 256;
    float* s_bias = s_b + 256;
    const int tid  = threadIdx.x;
    const int lane = tid & 31;
    const int warp = tid >> 5;
    const int wm = warp & 3;
    const int wn = warp >> 2;                          // 0..3
    const int row0 = blockIdx.x * 128;

    if (tid < 256) { s_g[tid] = lng[tid]; s_b[tid] = lnb[tid]; s_bias[tid] = bias[tid]; }

    float acc[2][8][4];
    #pragma unroll
    for (int i = 0; i < 2; i++)
        #pragma unroll
        for (int j = 0; j < 8; j++)
            #pragma unroll
            for (int k = 0; k < 4; k++) acc[i][j][k] = 0.f;

    gemm_ln_issue(sb, 0, tid, row0, 0, Ahi, Alo, Bhi, Blo);
    gemm_ln_issue(sb, 1, tid, row0, 32, Ahi, Alo, Bhi, Blo);

    for (int ch = 0; ch < 8; ch++) {
        if (ch < 7) cp_wait<1>(); else cp_wait<0>();
        __syncthreads();
        const uint32_t base = sb + (ch % 3) * LSTG;
        #pragma unroll
        for (int s = 0; s < 2; s++) {
            uint32_t ah[2][4], al[2][4];
            #pragma unroll
            for (int mt = 0; mt < 2; mt++) {
                int row = wm * 32 + mt * 16 + (lane & 15);
                int c = 2 * s + (lane >> 4);
                uint32_t off = (uint32_t)(row * 4 + (c ^ ((row >> 1) & 3))) * 16;
                ldsm_x4(ah[mt], base + off);
                ldsm_x4(al[mt], base + 8192 + off);
            }
            #pragma unroll
            for (int nt = 0; nt < 8; nt++) {
                int nr = wn * 64 + nt * 8 + (lane & 7);
                int c = 2 * s + ((lane >> 3) & 1);
                uint32_t off = (uint32_t)(nr * 4 + (c ^ ((nr >> 1) & 3))) * 16;
                uint32_t bh[2], bl[2];
                ldsm_x2(bh, base + 16384 + off);
                ldsm_x2(bl, base + 32768 + off);
                #pragma unroll
                for (int mt = 0; mt < 2; mt++) {
                    mma16816(acc[mt][nt], ah[mt], bh);
                    mma16816(acc[mt][nt], ah[mt], bl);
                    mma16816(acc[mt][nt], al[mt], bh);
                }
            }
        }
        __syncthreads();
        if (ch + 2 < 8)
            gemm_ln_issue(sb, (ch + 2) % 3, tid, row0, (ch + 2) * 32, Ahi, Alo, Bhi, Blo);
    }

    // ----- epilogue: bias + residual, LN stats, normalize, split-write -----
    const int g4 = lane >> 2, tig = lane & 3;
    float ps[2][2][2];
    #pragma unroll
    for (int mt = 0; mt < 2; mt++)
        #pragma unroll
        for (int h = 0; h < 2; h++) { ps[mt][h][0] = 0.f; ps[mt][h][1] = 0.f; }

    #pragma unroll
    for (int nt = 0; nt < 8; nt++) {
        int col = wn * 64 + nt * 8 + tig * 2;
        float b0 = s_bias[col], b1 = s_bias[col + 1];
        #pragma unroll
        for (int mt = 0; mt < 2; mt++) {
            size_t rA = (size_t)(row0 + wm * 32 + mt * 16 + g4) * 256 + col;
            uint32_t rh0 = *(const uint32_t*)(Xh + rA);
            uint32_t rl0 = *(const uint32_t*)(Xl + rA);
            uint32_t rh1 = *(const uint32_t*)(Xh + rA + 8 * 256);
            uint32_t rl1 = *(const uint32_t*)(Xl + rA + 8 * 256);
            float v0 = acc[mt][nt][0] + b0 + bflo(rh0) + bflo(rl0);
            float v1 = acc[mt][nt][1] + b1 + bfhi(rh0) + bfhi(rl0);
            float v2 = acc[mt][nt][2] + b0 + bflo(rh1) + bflo(rl1);
            float v3 = acc[mt][nt][3] + b1 + bfhi(rh1) + bfhi(rl1);
            acc[mt][nt][0] = v0; acc[mt][nt][1] = v1;
            acc[mt][nt][2] = v2; acc[mt][nt][3] = v3;
            ps[mt][0][0] += v0 + v1; ps[mt][0][1] += v0 * v0 + v1 * v1;
            ps[mt][1][0] += v2 + v3; ps[mt][1][1] += v2 * v2 + v3 * v3;
        }
    }
    #pragma unroll
    for (int mt = 0; mt < 2; mt++)
        #pragma unroll
        for (int h = 0; h < 2; h++) {
            ps[mt][h][0] += __shfl_xor_sync(0xffffffffu, ps[mt][h][0], 1);
            ps[mt][h][0] += __shfl_xor_sync(0xffffffffu, ps[mt][h][0], 2);
            ps[mt][h][1] += __shfl_xor_sync(0xffffffffu, ps[mt][h][1], 1);
            ps[mt][h][1] += __shfl_xor_sync(0xffffffffu, ps[mt][h][1], 2);
        }
    if (tig == 0) {
        #pragma unroll
        for (int mt = 0; mt < 2; mt++)
            #pragma unroll
            for (int h = 0; h < 2; h++) {
                int row = wm * 32 + mt * 16 + g4 + h * 8;
                *(float2*)&s_sum[(row * 4 + wn) * 2] =
                    make_float2(ps[mt][h][0], ps[mt][h][1]);
            }
    }
    __syncthreads();

    float mean[2][2], rstd[2][2];
    #pragma unroll
    for (int mt = 0; mt < 2; mt++)
        #pragma unroll
        for (int h = 0; h < 2; h++) {
            int row = wm * 32 + mt * 16 + g4 + h * 8;
            float s = 0.f, q = 0.f;
            #pragma unroll
            for (int w = 0; w < 4; w++) {
                float2 t = *(float2*)&s_sum[(row * 4 + w) * 2];
                s += t.x; q += t.y;
            }
            float m = s * (1.f / 256.f);
            float var = fmaxf(q * (1.f / 256.f) - m * m, 0.f);
            mean[mt][h] = m;
            rstd[mt][h] = rsqrtf(var + 1e-5f);
        }

    #pragma unroll
    for (int nt = 0; nt < 8; nt++) {
        int col = wn * 64 + nt * 8 + tig * 2;
        float gg0 = s_g[col], gg1 = s_g[col + 1];
        float bb0 = s_b[col], bb1 = s_b[col + 1];
        #pragma unroll
        for (int mt = 0; mt < 2; mt++) {
            size_t rA = (size_t)(row0 + wm * 32 + mt * 16 + g4) * 256 + col;
            float o0 = (acc[mt][nt][0] - mean[mt][0]) * rstd[mt][0] * gg0 + bb0;
            float o1 = (acc[mt][nt][1] - mean[mt][0]) * rstd[mt][0] * gg1 + bb1;
            float o2 = (acc[mt][nt][2] - mean[mt][1]) * rstd[mt][1] * gg0 + bb0;
            float o3 = (acc[mt][nt][3] - mean[mt][1]) * rstd[mt][1] * gg1 + bb1;
            uint32_t h01, l01, h23, l23;
            split2(o0, o1, h01, l01);
            split2(o2, o3, h23, l23);
            *(uint32_t*)(Xh + rA)           = h01;
            *(uint32_t*)(Xl + rA)           = l01;
            *(uint32_t*)(Xh + rA + 8 * 256) = h23;
            *(uint32_t*)(Xl + rA + 8 * 256) = l23;
        }
    }
}

// ---------------------------------------------------------------------------
// Weight transpose + split
// ---------------------------------------------------------------------------
__global__ void transpose_split(const float* __restrict__ B,
                                __nv_bfloat16* __restrict__ Thi,
                                __nv_bfloat16* __restrict__ Tlo,
                                int K, int N) {
    __shared__ float t[32][33];
    int n0 = blockIdx.x * 32, k0 = blockIdx.y * 32;
    int x = threadIdx.x, y = threadIdx.y;
    #pragma unroll
    for (int i = 0; i < 4; i++)
        t[y + i * 8][x] = B[(size_t)(k0 + y + i * 8) * N + n0 + x];
    __syncthreads();
    #pragma unroll
    for (int i = 0; i < 4; i++) {
        float v = t[x][y + i * 8];
        __nv_bfloat16 h, l;
        split1(v, h, l);
        size_t o = (size_t)(n0 + y + i * 8) * K + k0 + x;
        Thi[o] = h; Tlo[o] = l;
    }
}

// ---------------------------------------------------------------------------
// PE table + embedding (splits only)
// ---------------------------------------------------------------------------
__global__ void pe_kernel() {
    int s = blockIdx.x, d = threadIdx.x;
    int i2 = d >> 1;
    float div = expf((float)(2 * i2) * (-logf(10000.f) / (float)DIM));
    float arg = (float)s * div;
    g_PE[s * DIM + d] = (d & 1) ? cosf(arg) : sinf(arg);
}

__global__ void embed_kernel(const float* __restrict__ tok_emb,
                             const int* __restrict__ tokens) {
    int row = blockIdx.x;
    int s = row & (SEQ - 1);
    int d = threadIdx.x;
    int tok = tokens[row];
    float v = tok_emb[(size_t)tok * DIM + d] * 16.f + g_PE[s * DIM + d];
    size_t o = (size_t)row * DIM + d;
    __nv_bfloat16 h, l;
    split1(v, h, l);
    g_Xh[o] = h; g_Xl[o] = l;
}

// ---------------------------------------------------------------------------
// Attention
// ---------------------------------------------------------------------------
__global__ void attn_kernel() {
    int n = blockIdx.x >> 3;
    int h = blockIdx.x & 7;
    __shared__ float Qs[SEQ][DH + 1];
    __shared__ float Ks[SEQ][DH + 1];
    __shared__ float Vs[SEQ][DH + 1];
    const float* base = g_QKV + (size_t)n * SEQ * 3 * DIM;
    for (int e = threadIdx.x; e < SEQ * DH; e += blockDim.x) {
        int r = e >> 5, d = e & 31;
        Qs[r][d] = base[r * 3 * DIM + h * DH + d];
        Ks[r][d] = base[r * 3 * DIM + DIM + h * DH + d];
        Vs[r][d] = base[r * 3 * DIM + 2 * DIM + h * DH + d];
    }
    __syncthreads();
    int i = threadIdx.x;
    float q[DH];
    #pragma unroll
    for (int d = 0; d < DH; d++) q[d] = Qs[i][d];
    const float scale = 0.17677669529663687f;
    float m = -1e30f, l = 0.f;
    float o[DH];
    #pragma unroll
    for (int d = 0; d < DH; d++) o[d] = 0.f;
    for (int j = 0; j < SEQ; j++) {
        float s0 = 0.f, s1 = 0.f, s2 = 0.f, s3 = 0.f;
        #pragma unroll
        for (int d = 0; d < DH; d += 4) {
            s0 += q[d]     * Ks[j][d];
            s1 += q[d + 1] * Ks[j][d + 1];
            s2 += q[d + 2] * Ks[j][d + 2];
            s3 += q[d + 3] * Ks[j][d + 3];
        }
        float s = ((s0 + s1) + (s2 + s3)) * scale;
        if (s > m) {
            float c = expf(m - s);
            l *= c;
            #pragma unroll
            for (int d = 0; d < DH; d++) o[d] *= c;
            m = s;
        }
        float p = expf(s - m);
        l += p;
        #pragma unroll
        for (int d = 0; d < DH; d++) o[d] += p * Vs[j][d];
    }
    float inv = 1.f / l;
    size_t ob = ((size_t)n * SEQ + i) * DIM + h * DH;
    #pragma unroll
    for (int d = 0; d < DH; d += 2) {
        uint32_t hi, lo;
        split2(o[d] * inv, o[d + 1] * inv, hi, lo);
        *(uint32_t*)(g_T1h + ob + d) = hi;
        *(uint32_t*)(g_T1l + ob + d) = lo;
    }
}

// ---------------------------------------------------------------------------
// mean over seq + type emb (reads splits)
// ---------------------------------------------------------------------------
__global__ void mean_kernel(const int* __restrict__ types,
                            const float* __restrict__ type_emb) {
    int n = blockIdx.x, d = threadIdx.x;
    float acc = 0.f;
    const __nv_bfloat16* bh = g_Xh + (size_t)n * SEQ * DIM + d;
    const __nv_bfloat16* bl = g_Xl + (size_t)n * SEQ * DIM + d;
    for (int s = 0; s < SEQ; s++)
        acc += __bfloat162float(bh[s * DIM]) + __bfloat162float(bl[s * DIM]);
    float v = acc * (1.f / SEQ) + type_emb[(size_t)types[n] * DIM + d];
    size_t o = (size_t)n * DIM + d;
    g_H[o] = v;
    __nv_bfloat16 h, l;
    split1(v, h, l);
    g_Hh[o] = h; g_Hl[o] = l;
}

// ---------------------------------------------------------------------------
// GNN kernels — batched across relations
// ---------------------------------------------------------------------------
__global__ void asd_kernel(const float* __restrict__ asrc,
                           const float* __restrict__ adst) {
    int i = blockIdx.x;
    int w = threadIdx.x >> 5, lane = threadIdx.x & 31;
    float s1 = 0.f, s2 = 0.f;
    const float* xg = g_XG + (size_t)i * GHEADS * DIM + w * DIM;
    #pragma unroll
    for (int d = lane; d < DIM; d += 32) {
        float xv = xg[d];
        s1 += xv * asrc[w * DIM + d];
        s2 += xv * adst[w * DIM + d];
    }
    #pragma unroll
    for (int off = 16; off > 0; off >>= 1) {
        s1 += __shfl_down_sync(0xffffffffu, s1, off);
        s2 += __shfl_down_sync(0xffffffffu, s2, off);
    }
    if (lane == 0) {
        g_AS[i * GHEADS + w] = s1;
        g_AD[i * GHEADS + w] = s2;
        g_M[i * GHEADS + w] = lrelu(s1 + s2);
    }
}

__global__ void emax_kernel(const int* __restrict__ src, const int* __restrict__ dst,
                            const int* __restrict__ etype) {
    int e = blockIdx.x * blockDim.x + threadIdx.x;
    if (e >= NEDGE) return;
    int r = etype[e];
    int s = r * NN + src[e], t = r * NN + dst[e];
    #pragma unroll
    for (int gh = 0; gh < GHEADS; gh++) {
        float v = lrelu(g_AS[s * GHEADS + gh] + g_AD[t * GHEADS + gh]);
        atomicMaxF(&g_M[t * GHEADS + gh], v);
    }
}

__global__ void ninit_kernel() {
    int i = blockIdx.x, d = threadIdx.x;
    #pragma unroll
    for (int gh = 0; gh < GHEADS; gh++) {
        float es = lrelu(g_AS[i * GHEADS + gh] + g_AD[i * GHEADS + gh]);
        float ws = expf(es - g_M[i * GHEADS + gh]);
        g_NUM[(size_t)i * GHEADS * DIM + gh * DIM + d] =
            ws * g_XG[(size_t)i * GHEADS * DIM + gh * DIM + d];
        if (d == 0) g_DEN[i * GHEADS + gh] = ws;
    }
}

__global__ void eacc_kernel(const int* __restrict__ src, const int* __restrict__ dst,
                            const int* __restrict__ etype) {
    int e = blockIdx.x;
    int r = etype[e];
    int s = r * NN + src[e], t = r * NN + dst[e];
    int gh = threadIdx.x >> 6;
    int dd = threadIdx.x & 63;
    float w = expf(lrelu(g_AS[s * GHEADS + gh] + g_AD[t * GHEADS + gh])
                   - g_M[t * GHEADS + gh]);
    if (dd == 0) atomicAdd(&g_DEN[t * GHEADS + gh], w);
    const float* xs = g_XG + (size_t)s * GHEADS * DIM + gh * DIM;
    float* nm = g_NUM + (size_t)t * GHEADS * DIM + gh * DIM;
    #pragma unroll
    for (int k = 0; k < 4; k++) {
        int d = dd + 64 * k;
        atomicAdd(&nm[d], w * xs[d]);
    }
}

__global__ void combupd_kernel(const float* __restrict__ gb) {
    int n = blockIdx.x, d = threadIdx.x;
    float acc = 0.f;
    #pragma unroll
    for (int r = 0; r < NREL; r++) {
        int i = r * NN + n;
        #pragma unroll
        for (int gh = 0; gh < GHEADS; gh++)
            acc += g_NUM[(size_t)i * GHEADS * DIM + gh * DIM + d] / g_DEN[i * GHEADS + gh];
    }
    size_t o = (size_t)n * DIM + d;
    float v = fmaxf(g_H[o] + acc * 0.25f + 3.f * gb[d], 0.f);
    g_H[o] = v;
    __nv_bfloat16 h, l;
    split1(v, h, l);
    g_Hh[o] = h; g_Hl[o] = l;
}

__global__ void final_kernel(const float* __restrict__ log_c, float* __restrict__ out) {
    int n = blockIdx.x, d = threadIdx.x;
    __shared__ float sh[256];
    __shared__ float stat;
    float scale = sqrtf(expf(log_c[0]));
    float st = tanhf(g_TH[(size_t)n * DIM + d]) * 2.f * scale;
    sh[d] = st * st; __syncthreads();
    for (int s = 128; s > 0; s >>= 1) { if (d < s) sh[d] += sh[d + s]; __syncthreads(); }
    if (d == 0) stat = sh[0];
    __syncthreads();
    float r = fmaxf(sqrtf(stat), 1e-8f);
    if (d == 0) out[(size_t)n * 257] = coshf(r);
    out[(size_t)n * 257 + 1 + d] = sinhf(r) / r * st;
}

// ---------------------------------------------------------------------------
// Host orchestration
// ---------------------------------------------------------------------------
extern "C" void kernel_launch(void* const* d_in, const int* in_sizes, int n_in,
                              void* d_out, int out_size) {
    const float* tok_emb = (const float*)d_in[0];
    const float* Wqkv    = (const float*)d_in[1];
    const float* bqkv    = (const float*)d_in[2];
    const float* Wo      = (const float*)d_in[3];
    const float* bo      = (const float*)d_in[4];
    const float* ln1g    = (const float*)d_in[5];
    const float* ln1b    = (const float*)d_in[6];
    const float* ln2g    = (const float*)d_in[7];
    const float* ln2b    = (const float*)d_in[8];
    const float* W1      = (const float*)d_in[9];
    const float* b1      = (const float*)d_in[10];
    const float* W2      = (const float*)d_in[11];
    const float* b2      = (const float*)d_in[12];
    const float* type_emb= (const float*)d_in[13];
    const float* msg_W   = (const float*)d_in[14];
    const float* msg_b   = (const float*)d_in[15];
    const float* gat_W   = (const float*)d_in[16];
    const float* gat_b   = (const float*)d_in[17];
    const float* asrc    = (const float*)d_in[18];
    const float* adst    = (const float*)d_in[19];
    const float* spW1    = (const float*)d_in[20];
    const float* spb1    = (const float*)d_in[21];
    const float* spW2    = (const float*)d_in[22];
    const float* spb2    = (const float*)d_in[23];
    const float* log_c   = (const float*)d_in[24];
    const int*   tokens  = (const int*)d_in[25];
    const int*   types   = (const int*)d_in[26];
    const int*   eidx    = (const int*)d_in[27];
    const int*   etype   = (const int*)d_in[28];
    const int* esrc = eidx;
    const int* edst = eidx + NEDGE;
    float* out = (float*)d_out;

    float *pQKV, *pH, *pTH, *pXG;
    __nv_bfloat16 *pXh, *pXl, *pT1h, *pT1l, *pHh, *pHl, *pTHAh, *pTHAl,
                  *pSPHh, *pSPHl, *pWTh, *pWTl;
    cudaGetSymbolAddress((void**)&pQKV,  g_QKV);
    cudaGetSymbolAddress((void**)&pH,    g_H);
    cudaGetSymbolAddress((void**)&pTH,   g_TH);
    cudaGetSymbolAddress((void**)&pXG,   g_XG);
    cudaGetSymbolAddress((void**)&pXh,   g_Xh);
    cudaGetSymbolAddress((void**)&pXl,   g_Xl);
    cudaGetSymbolAddress((void**)&pT1h,  g_T1h);
    cudaGetSymbolAddress((void**)&pT1l,  g_T1l);
    cudaGetSymbolAddress((void**)&pHh,   g_Hh);
    cudaGetSymbolAddress((void**)&pHl,   g_Hl);
    cudaGetSymbolAddress((void**)&pTHAh, g_THAh);
    cudaGetSymbolAddress((void**)&pTHAl, g_THAl);
    cudaGetSymbolAddress((void**)&pSPHh, g_SPHh);
    cudaGetSymbolAddress((void**)&pSPHl, g_SPHl);
    cudaGetSymbolAddress((void**)&pWTh,  g_WTh);
    cudaGetSymbolAddress((void**)&pWTl,  g_WTl);

    cudaFuncSetAttribute(gemm_bf16, cudaFuncAttributeMaxDynamicSharedMemorySize,
                         NSTAGE * STAGE_BYTES);
    cudaFuncSetAttribute(gemm_ln, cudaFuncAttributeMaxDynamicSharedMemorySize,
                         3 * LSTG + 4096 + 3 * 1024);
    const int SMEM   = NSTAGE * STAGE_BYTES;
    const int SMEMLN = 3 * LSTG + 4096 + 3 * 1024;

    // 0) transpose + split all weights; PE table
    {
        dim3 blk(32, 8);
        for (int l = 0; l < 2; l++) {
            transpose_split<<<dim3(24, 8), blk>>>(Wqkv + (size_t)l * 256 * 768, pWTh + WT_QKV + l * 768 * 256, pWTl + WT_QKV + l * 768 * 256, 256, 768);
            transpose_split<<<dim3(8, 8), blk>>>(Wo + (size_t)l * 65536, pWTh + WT_WO + l * 65536, pWTl + WT_WO + l * 65536, 256, 256);
            transpose_split<<<dim3(8, 8), blk>>>(W1 + (size_t)l * 65536, pWTh + WT_W1 + l * 65536, pWTl + WT_W1 + l * 65536, 256, 256);
            transpose_split<<<dim3(8, 8), blk>>>(W2 + (size_t)l * 65536, pWTh + WT_W2 + l * 65536, pWTl + WT_W2 + l * 65536, 256, 256);
        }
        for (int r = 0; r < 3; r++)
            transpose_split<<<dim3(8, 8), blk>>>(msg_W + (size_t)r * 65536, pWTh + WT_MSG + r * 65536, pWTl + WT_MSG + r * 65536, 256, 256);
        for (int l = 0; l < 4; l++)
            transpose_split<<<dim3(32, 8), blk>>>(gat_W + (size_t)l * 256 * 1024, pWTh + WT_GAT + l * 1024 * 256, pWTl + WT_GAT + l * 1024 * 256, 256, 1024);
        transpose_split<<<dim3(16, 8), blk>>>(spW1, pWTh + WT_SP1, pWTl + WT_SP1, 256, 512);
        transpose_split<<<dim3(8, 16), blk>>>(spW2, pWTh + WT_SP2, pWTl + WT_SP2, 512, 256);
        pe_kernel<<<SEQ, 256>>>();
    }

    // 1) embedding + PE
    embed_kernel<<<NTOK, 256>>>(tok_emb, tokens);

    // 2) transformer encoder (LN fused into Wo / W2 GEMMs)
    for (int l = 0; l < 2; l++) {
        gemm_bf16<<<dim3(6, NTOK / 128), 256, SMEM>>>(
            pXh, pXl, 256, pWTh + WT_QKV + l * 768 * 256, pWTl + WT_QKV + l * 768 * 256,
            bqkv + l * 768, pQKV, nullptr, nullptr, NTOK, 768, 256, 0, 0);
        attn_kernel<<<NN * NH, 64>>>();
        gemm_ln<<<NTOK / 128, 512, SMEMLN>>>(
            pT1h, pT1l, pWTh + WT_WO + l * 65536, pWTl + WT_WO + l * 65536,
            bo + l * 256, ln1g + l * 256, ln1b + l * 256, pXh, pXl);
        gemm_bf16<<<dim3(2, NTOK / 128), 256, SMEM>>>(
            pXh, pXl, 256, pWTh + WT_W1 + l * 65536, pWTl + WT_W1 + l * 65536,
            b1 + l * 256, nullptr, pT1h, pT1l, NTOK, 256, 256, 1, 0);
        gemm_ln<<<NTOK / 128, 512, SMEMLN>>>(
            pT1h, pT1l, pWTh + WT_W2 + l * 65536, pWTl + WT_W2 + l * 65536,
            b2 + l * 256, ln2g + l * 256, ln2b + l * 256, pXh, pXl);
    }

    // 3) mean over seq + type embedding
    mean_kernel<<<NN, 256>>>(types, type_emb);

    // 4) 4 GNN layers (relations batched)
    for (int l = 0; l < 4; l++) {
        gemm_bf16<<<dim3(6, NN / 128), 256, SMEM>>>(
            pHh, pHl, 256, pWTh + WT_MSG, pWTl + WT_MSG,
            msg_b, nullptr, pTHAh, pTHAl, NN, 768, 256, 0, NN * DIM);
        gemm_bf16<<<dim3(8, NREL * NN / 128), 256, SMEM>>>(
            pTHAh, pTHAl, 256,
            pWTh + WT_GAT + l * 1024 * 256, pWTl + WT_GAT + l * 1024 * 256,
            nullptr, pXG, nullptr, nullptr, NREL * NN, 1024, 256, 0, 0);
        asd_kernel<<<NREL * NN, 128>>>(asrc + l * GHEADS * DIM, adst + l * GHEADS * DIM);
        emax_kernel<<<NEDGE / 128, 128>>>(esrc, edst, etype);
        ninit_kernel<<<NREL * NN, 256>>>();
        eacc_kernel<<<NEDGE, 256>>>(esrc, edst, etype);
        combupd_kernel<<<NN, 256>>>(gat_b + l * 256);
    }

    // 5) scoring MLP + Lorentz exp map
    gemm_bf16<<<dim3(4, NN / 128), 256, SMEM>>>(
        pHh, pHl, 256, pWTh + WT_SP1, pWTl + WT_SP1,
        spb1, nullptr, pSPHh, pSPHl, NN, 512, 256, 1, 0);
    gemm_bf16<<<dim3(2, NN / 128), 256, SMEM>>>(
        pSPHh, pSPHl, 512, pWTh + WT_SP2, pWTl + WT_SP2,
        spb2, pTH, nullptr, nullptr, NN, 256, 512, 0, 0);
    final_kernel<<<NN, 256>>>(log_c, out);
}

// round 7
// speedup vs baseline: 2.7040x; 1.0403x over previous
#include <cuda_runtime.h>
#include <cuda_bf16.h>
#include <math.h>
#include <stdint.h>

// ---------------------------------------------------------------------------
// Problem constants
// ---------------------------------------------------------------------------
#define NN      2048
#define SEQ     64
#define DIM     256
#define NH      8
#define DH      32
#define GHEADS  4
#define NEDGE   32768
#define NTOK    (NN*SEQ)
#define SPH     512
#define NREL    3
#define NSEG    (NREL*NN)     // 6144

// ---------------------------------------------------------------------------
// Scratch (device globals)
// ---------------------------------------------------------------------------
__device__ float g_QKV[NTOK*3*DIM];
__device__ float g_H  [NN*DIM];
__device__ float g_TH [NN*DIM];
__device__ float g_PE [SEQ*DIM];
__device__ float g_XG [NSEG*GHEADS*DIM];
__device__ float g_AS [NSEG*GHEADS];
__device__ float g_AD [NSEG*GHEADS];
__device__ float g_NUM[NSEG*GHEADS*DIM];   // normalized per-(rel,node) output

// CSR of edges sorted by (rel, dst) — built once
__device__ int g_off[NSEG + 1];
__device__ int g_pos[NSEG + 1];            // counts, then scatter cursors
__device__ int g_srt[NEDGE];               // src node per sorted edge

// bf16 hi/lo split activations
__device__ __nv_bfloat16 g_Xh [NTOK*DIM],  g_Xl [NTOK*DIM];
__device__ __nv_bfloat16 g_T1h[NTOK*DIM],  g_T1l[NTOK*DIM];
__device__ __nv_bfloat16 g_Hh [NN*DIM],    g_Hl [NN*DIM];
__device__ __nv_bfloat16 g_THAh[NREL*NN*DIM], g_THAl[NREL*NN*DIM];
__device__ __nv_bfloat16 g_SPHh[NN*SPH],   g_SPHl[NN*SPH];

// transposed + split weights, K-major [N, K]
#define WT_QKV   0
#define WT_WO    (WT_QKV + 2*768*256)
#define WT_W1    (WT_WO  + 2*256*256)
#define WT_W2    (WT_W1  + 2*256*256)
#define WT_MSG   (WT_W2  + 2*256*256)
#define WT_GAT   (WT_MSG + 3*256*256)
#define WT_SP1   (WT_GAT + 4*1024*256)
#define WT_SP2   (WT_SP1 + 512*256)
#define WT_TOTAL (WT_SP2 + 256*512)
__device__ __nv_bfloat16 g_WTh[WT_TOTAL], g_WTl[WT_TOTAL];

// ---------------------------------------------------------------------------
// Helpers
// ---------------------------------------------------------------------------
__device__ __forceinline__ float lrelu(float x) { return x > 0.f ? x : 0.2f * x; }

__device__ __forceinline__ uint32_t smem_u32(const void* p) {
    uint32_t a;
    asm("{ .reg .u64 t; cvta.to.shared.u64 t, %1; cvt.u32.u64 %0, t; }" : "=r"(a) : "l"(p));
    return a;
}

__device__ __forceinline__ void split1(float v, __nv_bfloat16& h, __nv_bfloat16& l) {
    h = __float2bfloat16_rn(v);
    l = __float2bfloat16_rn(v - __bfloat162float(h));
}

__device__ __forceinline__ void split2(float a, float b, uint32_t& hi, uint32_t& lo) {
    __nv_bfloat16 ha, la, hb, lb;
    split1(a, ha, la);
    split1(b, hb, lb);
    hi = (uint32_t)__bfloat16_as_ushort(ha) | ((uint32_t)__bfloat16_as_ushort(hb) << 16);
    lo = (uint32_t)__bfloat16_as_ushort(la) | ((uint32_t)__bfloat16_as_ushort(lb) << 16);
}

__device__ __forceinline__ float bflo(uint32_t x) {
    return __bfloat162float(__ushort_as_bfloat16((unsigned short)(x & 0xffffu)));
}
__device__ __forceinline__ float bfhi(uint32_t x) {
    return __bfloat162float(__ushort_as_bfloat16((unsigned short)(x >> 16)));
}

__device__ __forceinline__ void ldsm_x4(uint32_t* r, uint32_t a) {
    asm volatile("ldmatrix.sync.aligned.m8n8.x4.shared.b16 {%0,%1,%2,%3}, [%4];"
                 : "=r"(r[0]), "=r"(r[1]), "=r"(r[2]), "=r"(r[3]) : "r"(a));
}
__device__ __forceinline__ void ldsm_x2(uint32_t* r, uint32_t a) {
    asm volatile("ldmatrix.sync.aligned.m8n8.x2.shared.b16 {%0,%1}, [%2];"
                 : "=r"(r[0]), "=r"(r[1]) : "r"(a));
}

__device__ __forceinline__ void mma16816(float* c, const uint32_t* a, const uint32_t* b) {
    asm volatile(
        "mma.sync.aligned.m16n8k16.row.col.f32.bf16.bf16.f32 "
        "{%0,%1,%2,%3}, {%4,%5,%6,%7}, {%8,%9}, {%0,%1,%2,%3};"
        : "+f"(c[0]), "+f"(c[1]), "+f"(c[2]), "+f"(c[3])
        : "r"(a[0]), "r"(a[1]), "r"(a[2]), "r"(a[3]), "r"(b[0]), "r"(b[1]));
}

__device__ __forceinline__ void cp_async16(uint32_t dst, const void* src) {
    asm volatile("cp.async.cg.shared.global [%0], [%1], 16;" :: "r"(dst), "l"(src) : "memory");
}
__device__ __forceinline__ void cp_commit() {
    asm volatile("cp.async.commit_group;" ::: "memory");
}
template<int W> __device__ __forceinline__ void cp_wait() {
    asm volatile("cp.async.wait_group %0;" :: "n"(W) : "memory");
}

// ---------------------------------------------------------------------------
// Generic pipelined bf16-split GEMM (unchanged)
// ---------------------------------------------------------------------------
#define ARR_BYTES  8192
#define STAGE_BYTES (4*ARR_BYTES)
#define NSTAGE 3

__device__ __forceinline__ void gemm_issue(
    uint32_t sb, int stage, int tid,
    const __nv_bfloat16* Ahi, const __nv_bfloat16* Alo, int lda,
    const __nv_bfloat16* Bhi, const __nv_bfloat16* Blo, int K,
    int row0, int col0, int k0)
{
    #pragma unroll
    for (int i = 0; i < 8; i++) {
        int idx = tid + i * 256;
        int arr = idx >> 9;
        int j   = idx & 511;
        int r   = j >> 2;
        int c   = j & 3;
        uint32_t dst = sb + stage * STAGE_BYTES + arr * ARR_BYTES
                     + (uint32_t)(r * 4 + (c ^ ((r >> 1) & 3))) * 16;
        const __nv_bfloat16* src;
        if (arr == 0)      src = Ahi + (size_t)(row0 + r) * lda + k0 + c * 8;
        else if (arr == 1) src = Alo + (size_t)(row0 + r) * lda + k0 + c * 8;
        else if (arr == 2) src = Bhi + (size_t)(col0 + r) * K + k0 + c * 8;
        else               src = Blo + (size_t)(col0 + r) * K + k0 + c * 8;
        cp_async16(dst, src);
    }
    cp_commit();
}

__global__ void __launch_bounds__(256)
gemm_bf16(const __nv_bfloat16* __restrict__ Ahi, const __nv_bfloat16* __restrict__ Alo, int lda,
          const __nv_bfloat16* __restrict__ Bhi, const __nv_bfloat16* __restrict__ Blo,
          const float* __restrict__ bias,
          float* __restrict__ Cf,
          __nv_bfloat16* __restrict__ Chi, __nv_bfloat16* __restrict__ Clo,
          int M, int N, int K, int act, int rmaj) {
    extern __shared__ char sm[];
    const uint32_t sb = smem_u32(sm);
    const int tid  = threadIdx.x;
    const int lane = tid & 31;
    const int warp = tid >> 5;
    const int wm = warp & 3;
    const int wn = warp >> 2;
    const int row0 = blockIdx.y * 128;
    const int col0 = blockIdx.x * 128;

    float acc[2][8][4];
    #pragma unroll
    for (int i = 0; i < 2; i++)
        #pragma unroll
        for (int j = 0; j < 8; j++)
            #pragma unroll
            for (int k = 0; k < 4; k++) acc[i][j][k] = 0.f;

    const int nch = K >> 5;
    gemm_issue(sb, 0, tid, Ahi, Alo, lda, Bhi, Blo, K, row0, col0, 0);
    if (nch > 1)
        gemm_issue(sb, 1, tid, Ahi, Alo, lda, Bhi, Blo, K, row0, col0, 32);

    for (int ch = 0; ch < nch; ch++) {
        if (ch + 1 < nch) cp_wait<1>(); else cp_wait<0>();
        __syncthreads();

        const uint32_t base = sb + (ch % NSTAGE) * STAGE_BYTES;
        #pragma unroll
        for (int s = 0; s < 2; s++) {
            uint32_t ah[2][4], al[2][4];
            #pragma unroll
            for (int mt = 0; mt < 2; mt++) {
                int row = wm * 32 + mt * 16 + (lane & 15);
                int c = 2 * s + (lane >> 4);
                uint32_t off = (uint32_t)(row * 4 + (c ^ ((row >> 1) & 3))) * 16;
                ldsm_x4(ah[mt], base + off);
                ldsm_x4(al[mt], base + ARR_BYTES + off);
            }
            #pragma unroll
            for (int nt = 0; nt < 8; nt++) {
                int nr = wn * 64 + nt * 8 + (lane & 7);
                int c = 2 * s + ((lane >> 3) & 1);
                uint32_t off = (uint32_t)(nr * 4 + (c ^ ((nr >> 1) & 3))) * 16;
                uint32_t bh[2], bl[2];
                ldsm_x2(bh, base + 2 * ARR_BYTES + off);
                ldsm_x2(bl, base + 3 * ARR_BYTES + off);
                #pragma unroll
                for (int mt = 0; mt < 2; mt++) {
                    mma16816(acc[mt][nt], ah[mt], bh);
                    mma16816(acc[mt][nt], ah[mt], bl);
                    mma16816(acc[mt][nt], al[mt], bh);
                }
            }
        }
        __syncthreads();
        if (ch + 2 < nch)
            gemm_issue(sb, (ch + 2) % NSTAGE, tid, Ahi, Alo, lda, Bhi, Blo, K,
                       row0, col0, (ch + 2) << 5);
    }

    const int g4 = lane >> 2, tig = lane & 3;
    #pragma unroll
    for (int nt = 0; nt < 8; nt++) {
        int col = col0 + wn * 64 + nt * 8 + tig * 2;
        float b0 = 0.f, b1 = 0.f;
        if (bias) { b0 = bias[col]; b1 = bias[col + 1]; }
        #pragma unroll
        for (int mt = 0; mt < 2; mt++) {
            int row = row0 + wm * 32 + mt * 16 + g4;
            float v0 = acc[mt][nt][0] + b0;
            float v1 = acc[mt][nt][1] + b1;
            float v2 = acc[mt][nt][2] + b0;
            float v3 = acc[mt][nt][3] + b1;
            if (act) {
                v0 = fmaxf(v0, 0.f); v1 = fmaxf(v1, 0.f);
                v2 = fmaxf(v2, 0.f); v3 = fmaxf(v3, 0.f);
            }
            if (Cf) {
                *(float2*)(Cf + (size_t)row * N + col)       = make_float2(v0, v1);
                *(float2*)(Cf + (size_t)(row + 8) * N + col) = make_float2(v2, v3);
            }
            if (Chi) {
                uint32_t h01, l01, h23, l23;
                split2(v0, v1, h01, l01);
                split2(v2, v3, h23, l23);
                size_t o0, o1;
                if (rmaj) {
                    o0 = (size_t)(col >> 8) * rmaj + (size_t)row * 256 + (col & 255);
                    o1 = o0 + 8 * 256;
                } else {
                    o0 = (size_t)row * N + col;
                    o1 = o0 + (size_t)8 * N;
                }
                *(uint32_t*)(Chi + o0) = h01;
                *(uint32_t*)(Clo + o0) = l01;
                *(uint32_t*)(Chi + o1) = h23;
                *(uint32_t*)(Clo + o1) = l23;
            }
        }
    }
}

// ---------------------------------------------------------------------------
// Fused GEMM + residual + LayerNorm (unchanged from round 6)
// ---------------------------------------------------------------------------
#define LSTG 49152

__device__ __forceinline__ void gemm_ln_issue(
    uint32_t sb, int stage, int tid, int row0, int k0,
    const __nv_bfloat16* Ahi, const __nv_bfloat16* Alo,
    const __nv_bfloat16* Bhi, const __nv_bfloat16* Blo)
{
    #pragma unroll
    for (int i = 0; i < 6; i++) {
        int idx = tid + i * 512;
        uint32_t stg = sb + stage * LSTG;
        const __nv_bfloat16* src;
        uint32_t dst;
        if (idx < 1024) {
            int j = idx & 511;
            int r = j >> 2, c = j & 3;
            dst = stg + ((idx >> 9) ? 8192u : 0u)
                + (uint32_t)(r * 4 + (c ^ ((r >> 1) & 3))) * 16;
            src = ((idx >> 9) ? Alo : Ahi) + (size_t)(row0 + r) * 256 + k0 + c * 8;
        } else {
            int j = (idx - 1024) & 1023;
            int r = j >> 2, c = j & 3;
            dst = stg + ((idx >= 2048) ? 32768u : 16384u)
                + (uint32_t)(r * 4 + (c ^ ((r >> 1) & 3))) * 16;
            src = ((idx >= 2048) ? Blo : Bhi) + (size_t)r * 256 + k0 + c * 8;
        }
        cp_async16(dst, src);
    }
    cp_commit();
}

__global__ void __launch_bounds__(512)
gemm_ln(const __nv_bfloat16* __restrict__ Ahi, const __nv_bfloat16* __restrict__ Alo,
        const __nv_bfloat16* __restrict__ Bhi, const __nv_bfloat16* __restrict__ Blo,
        const float* __restrict__ bias,
        const float* __restrict__ lng, const float* __restrict__ lnb,
        __nv_bfloat16* Xh, __nv_bfloat16* Xl) {
    extern __shared__ char sm[];
    const uint32_t sb = smem_u32(sm);
    float* s_sum  = (float*)(sm + 3 * LSTG);
    float* s_g    = (float*)(sm + 3 * LSTG + 4096);
    float* s_b    = s_g + 256;
    float* s_bias = s_b + 256;
    const int tid  = threadIdx.x;
    const int lane = tid & 31;
    const int warp = tid >> 5;
    const int wm = warp & 3;
    const int wn = warp >> 2;
    const int row0 = blockIdx.x * 128;

    if (tid < 256) { s_g[tid] = lng[tid]; s_b[tid] = lnb[tid]; s_bias[tid] = bias[tid]; }

    float acc[2][8][4];
    #pragma unroll
    for (int i = 0; i < 2; i++)
        #pragma unroll
        for (int j = 0; j < 8; j++)
            #pragma unroll
            for (int k = 0; k < 4; k++) acc[i][j][k] = 0.f;

    gemm_ln_issue(sb, 0, tid, row0, 0, Ahi, Alo, Bhi, Blo);
    gemm_ln_issue(sb, 1, tid, row0, 32, Ahi, Alo, Bhi, Blo);

    for (int ch = 0; ch < 8; ch++) {
        if (ch < 7) cp_wait<1>(); else cp_wait<0>();
        __syncthreads();
        const uint32_t base = sb + (ch % 3) * LSTG;
        #pragma unroll
        for (int s = 0; s < 2; s++) {
            uint32_t ah[2][4], al[2][4];
            #pragma unroll
            for (int mt = 0; mt < 2; mt++) {
                int row = wm * 32 + mt * 16 + (lane & 15);
                int c = 2 * s + (lane >> 4);
                uint32_t off = (uint32_t)(row * 4 + (c ^ ((row >> 1) & 3))) * 16;
                ldsm_x4(ah[mt], base + off);
                ldsm_x4(al[mt], base + 8192 + off);
            }
            #pragma unroll
            for (int nt = 0; nt < 8; nt++) {
                int nr = wn * 64 + nt * 8 + (lane & 7);
                int c = 2 * s + ((lane >> 3) & 1);
                uint32_t off = (uint32_t)(nr * 4 + (c ^ ((nr >> 1) & 3))) * 16;
                uint32_t bh[2], bl[2];
                ldsm_x2(bh, base + 16384 + off);
                ldsm_x2(bl, base + 32768 + off);
                #pragma unroll
                for (int mt = 0; mt < 2; mt++) {
                    mma16816(acc[mt][nt], ah[mt], bh);
                    mma16816(acc[mt][nt], ah[mt], bl);
                    mma16816(acc[mt][nt], al[mt], bh);
                }
            }
        }
        __syncthreads();
        if (ch + 2 < 8)
            gemm_ln_issue(sb, (ch + 2) % 3, tid, row0, (ch + 2) * 32, Ahi, Alo, Bhi, Blo);
    }

    const int g4 = lane >> 2, tig = lane & 3;
    float ps[2][2][2];
    #pragma unroll
    for (int mt = 0; mt < 2; mt++)
        #pragma unroll
        for (int h = 0; h < 2; h++) { ps[mt][h][0] = 0.f; ps[mt][h][1] = 0.f; }

    #pragma unroll
    for (int nt = 0; nt < 8; nt++) {
        int col = wn * 64 + nt * 8 + tig * 2;
        float b0 = s_bias[col], b1 = s_bias[col + 1];
        #pragma unroll
        for (int mt = 0; mt < 2; mt++) {
            size_t rA = (size_t)(row0 + wm * 32 + mt * 16 + g4) * 256 + col;
            uint32_t rh0 = *(const uint32_t*)(Xh + rA);
            uint32_t rl0 = *(const uint32_t*)(Xl + rA);
            uint32_t rh1 = *(const uint32_t*)(Xh + rA + 8 * 256);
            uint32_t rl1 = *(const uint32_t*)(Xl + rA + 8 * 256);
            float v0 = acc[mt][nt][0] + b0 + bflo(rh0) + bflo(rl0);
            float v1 = acc[mt][nt][1] + b1 + bfhi(rh0) + bfhi(rl0);
            float v2 = acc[mt][nt][2] + b0 + bflo(rh1) + bflo(rl1);
            float v3 = acc[mt][nt][3] + b1 + bfhi(rh1) + bfhi(rl1);
            acc[mt][nt][0] = v0; acc[mt][nt][1] = v1;
            acc[mt][nt][2] = v2; acc[mt][nt][3] = v3;
            ps[mt][0][0] += v0 + v1; ps[mt][0][1] += v0 * v0 + v1 * v1;
            ps[mt][1][0] += v2 + v3; ps[mt][1][1] += v2 * v2 + v3 * v3;
        }
    }
    #pragma unroll
    for (int mt = 0; mt < 2; mt++)
        #pragma unroll
        for (int h = 0; h < 2; h++) {
            ps[mt][h][0] += __shfl_xor_sync(0xffffffffu, ps[mt][h][0], 1);
            ps[mt][h][0] += __shfl_xor_sync(0xffffffffu, ps[mt][h][0], 2);
            ps[mt][h][1] += __shfl_xor_sync(0xffffffffu, ps[mt][h][1], 1);
            ps[mt][h][1] += __shfl_xor_sync(0xffffffffu, ps[mt][h][1], 2);
        }
    if (tig == 0) {
        #pragma unroll
        for (int mt = 0; mt < 2; mt++)
            #pragma unroll
            for (int h = 0; h < 2; h++) {
                int row = wm * 32 + mt * 16 + g4 + h * 8;
                *(float2*)&s_sum[(row * 4 + wn) * 2] =
                    make_float2(ps[mt][h][0], ps[mt][h][1]);
            }
    }
    __syncthreads();

    float mean[2][2], rstd[2][2];
    #pragma unroll
    for (int mt = 0; mt < 2; mt++)
        #pragma unroll
        for (int h = 0; h < 2; h++) {
            int row = wm * 32 + mt * 16 + g4 + h * 8;
            float s = 0.f, q = 0.f;
            #pragma unroll
            for (int w = 0; w < 4; w++) {
                float2 t = *(float2*)&s_sum[(row * 4 + w) * 2];
                s += t.x; q += t.y;
            }
            float m = s * (1.f / 256.f);
            float var = fmaxf(q * (1.f / 256.f) - m * m, 0.f);
            mean[mt][h] = m;
            rstd[mt][h] = rsqrtf(var + 1e-5f);
        }

    #pragma unroll
    for (int nt = 0; nt < 8; nt++) {
        int col = wn * 64 + nt * 8 + tig * 2;
        float gg0 = s_g[col], gg1 = s_g[col + 1];
        float bb0 = s_b[col], bb1 = s_b[col + 1];
        #pragma unroll
        for (int mt = 0; mt < 2; mt++) {
            size_t rA = (size_t)(row0 + wm * 32 + mt * 16 + g4) * 256 + col;
            float o0 = (acc[mt][nt][0] - mean[mt][0]) * rstd[mt][0] * gg0 + bb0;
            float o1 = (acc[mt][nt][1] - mean[mt][0]) * rstd[mt][0] * gg1 + bb1;
            float o2 = (acc[mt][nt][2] - mean[mt][1]) * rstd[mt][1] * gg0 + bb0;
            float o3 = (acc[mt][nt][3] - mean[mt][1]) * rstd[mt][1] * gg1 + bb1;
            uint32_t h01, l01, h23, l23;
            split2(o0, o1, h01, l01);
            split2(o2, o3, h23, l23);
            *(uint32_t*)(Xh + rA)           = h01;
            *(uint32_t*)(Xl + rA)           = l01;
            *(uint32_t*)(Xh + rA + 8 * 256) = h23;
            *(uint32_t*)(Xl + rA + 8 * 256) = l23;
        }
    }
}

// ---------------------------------------------------------------------------
// Weight transpose + split
// ---------------------------------------------------------------------------
__global__ void transpose_split(const float* __restrict__ B,
                                __nv_bfloat16* __restrict__ Thi,
                                __nv_bfloat16* __restrict__ Tlo,
                                int K, int N) {
    __shared__ float t[32][33];
    int n0 = blockIdx.x * 32, k0 = blockIdx.y * 32;
    int x = threadIdx.x, y = threadIdx.y;
    #pragma unroll
    for (int i = 0; i < 4; i++)
        t[y + i * 8][x] = B[(size_t)(k0 + y + i * 8) * N + n0 + x];
    __syncthreads();
    #pragma unroll
    for (int i = 0; i < 4; i++) {
        float v = t[x][y + i * 8];
        __nv_bfloat16 h, l;
        split1(v, h, l);
        size_t o = (size_t)(n0 + y + i * 8) * K + k0 + x;
        Thi[o] = h; Tlo[o] = l;
    }
}

// ---------------------------------------------------------------------------
// CSR build (once): counts -> scan -> scatter
// ---------------------------------------------------------------------------
__global__ void csr_count(const int* __restrict__ dst, const int* __restrict__ etype) {
    int e = blockIdx.x * blockDim.x + threadIdx.x;
    if (e >= NEDGE) return;
    atomicAdd(&g_pos[etype[e] * NN + dst[e]], 1);
}

__global__ void __launch_bounds__(1024) csr_scan() {
    __shared__ int s[1024];
    const int tid = threadIdx.x;
    const int base = tid * 6;           // 1024*6 = 6144 = NSEG
    int local[6];
    int sum = 0;
    #pragma unroll
    for (int k = 0; k < 6; k++) { local[k] = sum; sum += g_pos[base + k]; }
    s[tid] = sum;
    __syncthreads();
    for (int d = 1; d < 1024; d <<= 1) {
        int v = (tid >= d) ? s[tid - d] : 0;
        __syncthreads();
        s[tid] += v;
        __syncthreads();
    }
    int pre = s[tid] - sum;             // exclusive prefix of this thread's chunk
    #pragma unroll
    for (int k = 0; k < 6; k++) {
        g_off[base + k] = pre + local[k];
        g_pos[base + k] = pre + local[k];   // scatter cursor
    }
    if (tid == 1023) g_off[NSEG] = s[1023];
}

__global__ void csr_scatter(const int* __restrict__ src, const int* __restrict__ dst,
                            const int* __restrict__ etype) {
    int e = blockIdx.x * blockDim.x + threadIdx.x;
    if (e >= NEDGE) return;
    int p = atomicAdd(&g_pos[etype[e] * NN + dst[e]], 1);
    g_srt[p] = src[e];
}

// ---------------------------------------------------------------------------
// PE table + embedding
// ---------------------------------------------------------------------------
__global__ void pe_kernel() {
    int s = blockIdx.x, d = threadIdx.x;
    int i2 = d >> 1;
    float div = expf((float)(2 * i2) * (-logf(10000.f) / (float)DIM));
    float arg = (float)s * div;
    g_PE[s * DIM + d] = (d & 1) ? cosf(arg) : sinf(arg);
}

__global__ void embed_kernel(const float* __restrict__ tok_emb,
                             const int* __restrict__ tokens) {
    int row = blockIdx.x;
    int s = row & (SEQ - 1);
    int d = threadIdx.x;
    int tok = tokens[row];
    float v = tok_emb[(size_t)tok * DIM + d] * 16.f + g_PE[s * DIM + d];
    size_t o = (size_t)row * DIM + d;
    __nv_bfloat16 h, l;
    split1(v, h, l);
    g_Xh[o] = h; g_Xl[o] = l;
}

// ---------------------------------------------------------------------------
// Attention
// ---------------------------------------------------------------------------
__global__ void attn_kernel() {
    int n = blockIdx.x >> 3;
    int h = blockIdx.x & 7;
    __shared__ float Qs[SEQ][DH + 1];
    __shared__ float Ks[SEQ][DH + 1];
    __shared__ float Vs[SEQ][DH + 1];
    const float* base = g_QKV + (size_t)n * SEQ * 3 * DIM;
    for (int e = threadIdx.x; e < SEQ * DH; e += blockDim.x) {
        int r = e >> 5, d = e & 31;
        Qs[r][d] = base[r * 3 * DIM + h * DH + d];
        Ks[r][d] = base[r * 3 * DIM + DIM + h * DH + d];
        Vs[r][d] = base[r * 3 * DIM + 2 * DIM + h * DH + d];
    }
    __syncthreads();
    int i = threadIdx.x;
    float q[DH];
    #pragma unroll
    for (int d = 0; d < DH; d++) q[d] = Qs[i][d];
    const float scale = 0.17677669529663687f;
    float m = -1e30f, l = 0.f;
    float o[DH];
    #pragma unroll
    for (int d = 0; d < DH; d++) o[d] = 0.f;
    for (int j = 0; j < SEQ; j++) {
        float s0 = 0.f, s1 = 0.f, s2 = 0.f, s3 = 0.f;
        #pragma unroll
        for (int d = 0; d < DH; d += 4) {
            s0 += q[d]     * Ks[j][d];
            s1 += q[d + 1] * Ks[j][d + 1];
            s2 += q[d + 2] * Ks[j][d + 2];
            s3 += q[d + 3] * Ks[j][d + 3];
        }
        float s = ((s0 + s1) + (s2 + s3)) * scale;
        if (s > m) {
            float c = expf(m - s);
            l *= c;
            #pragma unroll
            for (int d = 0; d < DH; d++) o[d] *= c;
            m = s;
        }
        float p = expf(s - m);
        l += p;
        #pragma unroll
        for (int d = 0; d < DH; d++) o[d] += p * Vs[j][d];
    }
    float inv = 1.f / l;
    size_t ob = ((size_t)n * SEQ + i) * DIM + h * DH;
    #pragma unroll
    for (int d = 0; d < DH; d += 2) {
        uint32_t hi, lo;
        split2(o[d] * inv, o[d + 1] * inv, hi, lo);
        *(uint32_t*)(g_T1h + ob + d) = hi;
        *(uint32_t*)(g_T1l + ob + d) = lo;
    }
}

// ---------------------------------------------------------------------------
// mean over seq + type emb
// ---------------------------------------------------------------------------
__global__ void mean_kernel(const int* __restrict__ types,
                            const float* __restrict__ type_emb) {
    int n = blockIdx.x, d = threadIdx.x;
    float acc = 0.f;
    const __nv_bfloat16* bh = g_Xh + (size_t)n * SEQ * DIM + d;
    const __nv_bfloat16* bl = g_Xl + (size_t)n * SEQ * DIM + d;
    for (int s = 0; s < SEQ; s++)
        acc += __bfloat162float(bh[s * DIM]) + __bfloat162float(bl[s * DIM]);
    float v = acc * (1.f / SEQ) + type_emb[(size_t)types[n] * DIM + d];
    size_t o = (size_t)n * DIM + d;
    g_H[o] = v;
    __nv_bfloat16 h, l;
    split1(v, h, l);
    g_Hh[o] = h; g_Hl[o] = l;
}

// ---------------------------------------------------------------------------
// GNN kernels
// ---------------------------------------------------------------------------
__global__ void asd_kernel(const float* __restrict__ asrc,
                           const float* __restrict__ adst) {
    int i = blockIdx.x;
    int w = threadIdx.x >> 5, lane = threadIdx.x & 31;
    float s1 = 0.f, s2 = 0.f;
    const float* xg = g_XG + (size_t)i * GHEADS * DIM + w * DIM;
    #pragma unroll
    for (int d = lane; d < DIM; d += 32) {
        float xv = xg[d];
        s1 += xv * asrc[w * DIM + d];
        s2 += xv * adst[w * DIM + d];
    }
    #pragma unroll
    for (int off = 16; off > 0; off >>= 1) {
        s1 += __shfl_down_sync(0xffffffffu, s1, off);
        s2 += __shfl_down_sync(0xffffffffu, s2, off);
    }
    if (lane == 0) {
        g_AS[i * GHEADS + w] = s1;
        g_AD[i * GHEADS + w] = s2;
    }
}

// CSR-based GAT aggregation: per (rel*NN+node), per head (warp):
// m = max(self, edges); w = exp(e - m); NUM = (sum w*x_src + w_self*x_self)/den
__global__ void __launch_bounds__(128) csr_agg() {
    const int i = blockIdx.x;                 // r*NN + n
    const int w = threadIdx.x >> 5;
    const int lane = threadIdx.x & 31;
    const int rbase = (i >> 11) << 11;        // (i/NN)*NN, NN=2048
    const int beg = g_off[i], end = g_off[i + 1];

    const float ad = g_AD[i * GHEADS + w];
    const float self_e = lrelu(g_AS[i * GHEADS + w] + ad);

    // segment max
    float m = self_e;
    for (int j = beg + lane; j < end; j += 32)
        m = fmaxf(m, lrelu(g_AS[(rbase + g_srt[j]) * GHEADS + w] + ad));
    #pragma unroll
    for (int off = 16; off > 0; off >>= 1)
        m = fmaxf(m, __shfl_xor_sync(0xffffffffu, m, off));

    // accumulate
    float den = expf(self_e - m);
    float acc[8];
    const float* xs = g_XG + (size_t)i * (GHEADS * DIM) + w * DIM;
    #pragma unroll
    for (int k = 0; k < 8; k++) acc[k] = den * xs[lane + 32 * k];
    for (int j = beg; j < end; j++) {
        int s = rbase + g_srt[j];
        float wgt = expf(lrelu(g_AS[s * GHEADS + w] + ad) - m);
        den += wgt;
        const float* xv = g_XG + (size_t)s * (GHEADS * DIM) + w * DIM;
        #pragma unroll
        for (int k = 0; k < 8; k++) acc[k] += wgt * xv[lane + 32 * k];
    }
    float inv = 1.f / den;
    float* nm = g_NUM + (size_t)i * (GHEADS * DIM) + w * DIM;
    #pragma unroll
    for (int k = 0; k < 8; k++) nm[lane + 32 * k] = acc[k] * inv;
}

// h = relu(h + sum_r mean_gh(NUM) + 3*gb); NUM already normalized.
__global__ void combupd_kernel(const float* __restrict__ gb) {
    int n = blockIdx.x, d = threadIdx.x;
    float acc = 0.f;
    #pragma unroll
    for (int r = 0; r < NREL; r++) {
        int i = r * NN + n;
        #pragma unroll
        for (int gh = 0; gh < GHEADS; gh++)
            acc += g_NUM[(size_t)i * GHEADS * DIM + gh * DIM + d];
    }
    size_t o = (size_t)n * DIM + d;
    float v = fmaxf(g_H[o] + acc * 0.25f + 3.f * gb[d], 0.f);
    g_H[o] = v;
    __nv_bfloat16 h, l;
    split1(v, h, l);
    g_Hh[o] = h; g_Hl[o] = l;
}

__global__ void final_kernel(const float* __restrict__ log_c, float* __restrict__ out) {
    int n = blockIdx.x, d = threadIdx.x;
    __shared__ float sh[256];
    __shared__ float stat;
    float scale = sqrtf(expf(log_c[0]));
    float st = tanhf(g_TH[(size_t)n * DIM + d]) * 2.f * scale;
    sh[d] = st * st; __syncthreads();
    for (int s = 128; s > 0; s >>= 1) { if (d < s) sh[d] += sh[d + s]; __syncthreads(); }
    if (d == 0) stat = sh[0];
    __syncthreads();
    float r = fmaxf(sqrtf(stat), 1e-8f);
    if (d == 0) out[(size_t)n * 257] = coshf(r);
    out[(size_t)n * 257 + 1 + d] = sinhf(r) / r * st;
}

// ---------------------------------------------------------------------------
// Host orchestration
// ---------------------------------------------------------------------------
extern "C" void kernel_launch(void* const* d_in, const int* in_sizes, int n_in,
                              void* d_out, int out_size) {
    const float* tok_emb = (const float*)d_in[0];
    const float* Wqkv    = (const float*)d_in[1];
    const float* bqkv    = (const float*)d_in[2];
    const float* Wo      = (const float*)d_in[3];
    const float* bo      = (const float*)d_in[4];
    const float* ln1g    = (const float*)d_in[5];
    const float* ln1b    = (const float*)d_in[6];
    const float* ln2g    = (const float*)d_in[7];
    const float* ln2b    = (const float*)d_in[8];
    const float* W1      = (const float*)d_in[9];
    const float* b1      = (const float*)d_in[10];
    const float* W2      = (const float*)d_in[11];
    const float* b2      = (const float*)d_in[12];
    const float* type_emb= (const float*)d_in[13];
    const float* msg_W   = (const float*)d_in[14];
    const float* msg_b   = (const float*)d_in[15];
    const float* gat_W   = (const float*)d_in[16];
    const float* gat_b   = (const float*)d_in[17];
    const float* asrc    = (const float*)d_in[18];
    const float* adst    = (const float*)d_in[19];
    const float* spW1    = (const float*)d_in[20];
    const float* spb1    = (const float*)d_in[21];
    const float* spW2    = (const float*)d_in[22];
    const float* spb2    = (const float*)d_in[23];
    const float* log_c   = (const float*)d_in[24];
    const int*   tokens  = (const int*)d_in[25];
    const int*   types   = (const int*)d_in[26];
    const int*   eidx    = (const int*)d_in[27];
    const int*   etype   = (const int*)d_in[28];
    const int* esrc = eidx;
    const int* edst = eidx + NEDGE;
    float* out = (float*)d_out;

    float *pQKV, *pH, *pTH, *pXG;
    int *pPos;
    __nv_bfloat16 *pXh, *pXl, *pT1h, *pT1l, *pHh, *pHl, *pTHAh, *pTHAl,
                  *pSPHh, *pSPHl, *pWTh, *pWTl;
    cudaGetSymbolAddress((void**)&pQKV,  g_QKV);
    cudaGetSymbolAddress((void**)&pH,    g_H);
    cudaGetSymbolAddress((void**)&pTH,   g_TH);
    cudaGetSymbolAddress((void**)&pXG,   g_XG);
    cudaGetSymbolAddress((void**)&pPos,  g_pos);
    cudaGetSymbolAddress((void**)&pXh,   g_Xh);
    cudaGetSymbolAddress((void**)&pXl,   g_Xl);
    cudaGetSymbolAddress((void**)&pT1h,  g_T1h);
    cudaGetSymbolAddress((void**)&pT1l,  g_T1l);
    cudaGetSymbolAddress((void**)&pHh,   g_Hh);
    cudaGetSymbolAddress((void**)&pHl,   g_Hl);
    cudaGetSymbolAddress((void**)&pTHAh, g_THAh);
    cudaGetSymbolAddress((void**)&pTHAl, g_THAl);
    cudaGetSymbolAddress((void**)&pSPHh, g_SPHh);
    cudaGetSymbolAddress((void**)&pSPHl, g_SPHl);
    cudaGetSymbolAddress((void**)&pWTh,  g_WTh);
    cudaGetSymbolAddress((void**)&pWTl,  g_WTl);

    cudaFuncSetAttribute(gemm_bf16, cudaFuncAttributeMaxDynamicSharedMemorySize,
                         NSTAGE * STAGE_BYTES);
    cudaFuncSetAttribute(gemm_ln, cudaFuncAttributeMaxDynamicSharedMemorySize,
                         3 * LSTG + 4096 + 3 * 1024);
    const int SMEM   = NSTAGE * STAGE_BYTES;
    const int SMEMLN = 3 * LSTG + 4096 + 3 * 1024;

    // 0) transpose + split all weights; PE table; CSR build (once)
    {
        dim3 blk(32, 8);
        for (int l = 0; l < 2; l++) {
            transpose_split<<<dim3(24, 8), blk>>>(Wqkv + (size_t)l * 256 * 768, pWTh + WT_QKV + l * 768 * 256, pWTl + WT_QKV + l * 768 * 256, 256, 768);
            transpose_split<<<dim3(8, 8), blk>>>(Wo + (size_t)l * 65536, pWTh + WT_WO + l * 65536, pWTl + WT_WO + l * 65536, 256, 256);
            transpose_split<<<dim3(8, 8), blk>>>(W1 + (size_t)l * 65536, pWTh + WT_W1 + l * 65536, pWTl + WT_W1 + l * 65536, 256, 256);
            transpose_split<<<dim3(8, 8), blk>>>(W2 + (size_t)l * 65536, pWTh + WT_W2 + l * 65536, pWTl + WT_W2 + l * 65536, 256, 256);
        }
        for (int r = 0; r < 3; r++)
            transpose_split<<<dim3(8, 8), blk>>>(msg_W + (size_t)r * 65536, pWTh + WT_MSG + r * 65536, pWTl + WT_MSG + r * 65536, 256, 256);
        for (int l = 0; l < 4; l++)
            transpose_split<<<dim3(32, 8), blk>>>(gat_W + (size_t)l * 256 * 1024, pWTh + WT_GAT + l * 1024 * 256, pWTl + WT_GAT + l * 1024 * 256, 256, 1024);
        transpose_split<<<dim3(16, 8), blk>>>(spW1, pWTh + WT_SP1, pWTl + WT_SP1, 256, 512);
        transpose_split<<<dim3(8, 16), blk>>>(spW2, pWTh + WT_SP2, pWTl + WT_SP2, 512, 256);
        pe_kernel<<<SEQ, 256>>>();

        cudaMemsetAsync(pPos, 0, (NSEG + 1) * sizeof(int));
        csr_count<<<NEDGE / 256, 256>>>(edst, etype);
        csr_scan<<<1, 1024>>>();
        csr_scatter<<<NEDGE / 256, 256>>>(esrc, edst, etype);
    }

    // 1) embedding + PE
    embed_kernel<<<NTOK, 256>>>(tok_emb, tokens);

    // 2) transformer encoder (LN fused into Wo / W2 GEMMs)
    for (int l = 0; l < 2; l++) {
        gemm_bf16<<<dim3(6, NTOK / 128), 256, SMEM>>>(
            pXh, pXl, 256, pWTh + WT_QKV + l * 768 * 256, pWTl + WT_QKV + l * 768 * 256,
            bqkv + l * 768, pQKV, nullptr, nullptr, NTOK, 768, 256, 0, 0);
        attn_kernel<<<NN * NH, 64>>>();
        gemm_ln<<<NTOK / 128, 512, SMEMLN>>>(
            pT1h, pT1l, pWTh + WT_WO + l * 65536, pWTl + WT_WO + l * 65536,
            bo + l * 256, ln1g + l * 256, ln1b + l * 256, pXh, pXl);
        gemm_bf16<<<dim3(2, NTOK / 128), 256, SMEM>>>(
            pXh, pXl, 256, pWTh + WT_W1 + l * 65536, pWTl + WT_W1 + l * 65536,
            b1 + l * 256, nullptr, pT1h, pT1l, NTOK, 256, 256, 1, 0);
        gemm_ln<<<NTOK / 128, 512, SMEMLN>>>(
            pT1h, pT1l, pWTh + WT_W2 + l * 65536, pWTl + WT_W2 + l * 65536,
            b2 + l * 256, ln2g + l * 256, ln2b + l * 256, pXh, pXl);
    }

    // 3) mean over seq + type embedding
    mean_kernel<<<NN, 256>>>(types, type_emb);

    // 4) 4 GNN layers (relations batched; CSR aggregation, no atomics)
    for (int l = 0; l < 4; l++) {
        gemm_bf16<<<dim3(6, NN / 128), 256, SMEM>>>(
            pHh, pHl, 256, pWTh + WT_MSG, pWTl + WT_MSG,
            msg_b, nullptr, pTHAh, pTHAl, NN, 768, 256, 0, NN * DIM);
        gemm_bf16<<<dim3(8, NREL * NN / 128), 256, SMEM>>>(
            pTHAh, pTHAl, 256,
            pWTh + WT_GAT + l * 1024 * 256, pWTl + WT_GAT + l * 1024 * 256,
            nullptr, pXG, nullptr, nullptr, NREL * NN, 1024, 256, 0, 0);
        asd_kernel<<<NSEG, 128>>>(asrc + l * GHEADS * DIM, adst + l * GHEADS * DIM);
        csr_agg<<<NSEG, 128>>>();
        combupd_kernel<<<NN, 256>>>(gat_b + l * 256);
    }

    // 5) scoring MLP + Lorentz exp map
    gemm_bf16<<<dim3(4, NN / 128), 256, SMEM>>>(
        pHh, pHl, 256, pWTh + WT_SP1, pWTl + WT_SP1,
        spb1, nullptr, pSPHh, pSPHl, NN, 512, 256, 1, 0);
    gemm_bf16<<<dim3(2, NN / 128), 256, SMEM>>>(
        pSPHh, pSPHl, 512, pWTh + WT_SP2, pWTl + WT_SP2,
        spb2, pTH, nullptr, nullptr, NN, 256, 512, 0, 0);
    final_kernel<<<NN, 256>>>(log_c, out);
}